// round 1
// baseline (speedup 1.0000x reference)
#include <cuda_runtime.h>

constexpr int NB = 4;      // batch
constexpr int NC = 1024;   // channels
constexpr int NT = 2048;   // time
constexpr int NH = 16;     // heads
constexpr int NG = 32;     // groups
constexpr int CPG = NC / NG;   // 32 channels per group
constexpr int CH  = NC / NH;   // 64 channels per head
constexpr float EPS = 1e-5f;

// Scratch (device globals — no allocation inside kernel_launch)
__device__ float g_xn[NB * NC * NT];        // 32 MB
__device__ float g_qkv[NB * 3 * NC * NT];   // 96 MB
__device__ float g_attn[NB * NC * NT];      // 32 MB

// ---------------------------------------------------------------------------
// GroupNorm(32, C): one block per (b, g). Group data is contiguous (32*2048
// floats). Pass 1 reduces sum/sumsq; pass 2 re-reads (L2 hit) and normalizes.
// ---------------------------------------------------------------------------
__global__ void gn_kernel(const float* __restrict__ x,
                          const float* __restrict__ gamma,
                          const float* __restrict__ beta,
                          float* __restrict__ xn) {
    const int b = blockIdx.x / NG;
    const int g = blockIdx.x % NG;
    const int n = CPG * NT;                       // 65536
    const size_t base = ((size_t)b * NC + (size_t)g * CPG) * NT;
    const float4* xv = reinterpret_cast<const float4*>(x + base);
    float4* ov = reinterpret_cast<float4*>(xn + base);
    const int nv = n / 4;                         // 16384

    float s = 0.f, sq = 0.f;
    for (int i = threadIdx.x; i < nv; i += blockDim.x) {
        float4 v = xv[i];
        s  += v.x + v.y + v.z + v.w;
        sq += v.x * v.x + v.y * v.y + v.z * v.z + v.w * v.w;
    }
    __shared__ float ss[512], sq2[512];
    ss[threadIdx.x] = s; sq2[threadIdx.x] = sq;
    __syncthreads();
    for (int o = blockDim.x >> 1; o > 0; o >>= 1) {
        if (threadIdx.x < (unsigned)o) {
            ss[threadIdx.x]  += ss[threadIdx.x + o];
            sq2[threadIdx.x] += sq2[threadIdx.x + o];
        }
        __syncthreads();
    }
    __shared__ float smean, srstd;
    if (threadIdx.x == 0) {
        float m   = ss[0] / n;
        float var = sq2[0] / n - m * m;
        smean = m;
        srstd = rsqrtf(var + EPS);
    }
    __syncthreads();
    const float m = smean, r = srstd;
    for (int i = threadIdx.x; i < nv; i += blockDim.x) {
        int c = g * CPG + (i >> 9);               // (i*4)/NT, NT=2048
        float sc = gamma[c] * r;
        float bi = beta[c] - m * sc;
        float4 v = xv[i];
        float4 o;
        o.x = v.x * sc + bi; o.y = v.y * sc + bi;
        o.z = v.z * sc + bi; o.w = v.w * sc + bi;
        ov[i] = o;
    }
}

// ---------------------------------------------------------------------------
// Classic fp32 SGEMM: C[bz] = A (MxK, row-major, batch-shared) * B[bz] (KxN,
// row stride N) + bias[row]  (+ resid[bz] when MODE==1).
// 128x128 block tile, BK=8, 256 threads, 8x8 per thread.
// All dims here are multiples of 128/8 — no bounds checks.
// ---------------------------------------------------------------------------
template <int MODE>
__global__ void sgemm128(const float* __restrict__ A,
                         const float* __restrict__ Bm,
                         const float* __restrict__ bias,
                         const float* __restrict__ resid,
                         float* __restrict__ Cm,
                         int M, int N, int K,
                         long strideB, long strideC, long strideR) {
    __shared__ float As[8][128];
    __shared__ float Bs[8][128];
    const int tid = threadIdx.x;
    const int tx = tid & 15, ty = tid >> 4;
    const int m0 = blockIdx.y * 128, n0 = blockIdx.x * 128;
    const float* Bp = Bm + (size_t)blockIdx.z * strideB;
    float* Cp = Cm + (size_t)blockIdx.z * strideC;

    const int arow = tid >> 1, acol = (tid & 1) << 2;
    const int brow = tid >> 5, bcol = (tid & 31) << 2;
    const float* Aptr = A + (size_t)(m0 + arow) * K + acol;
    const float* Bptr = Bp + (size_t)brow * N + n0 + bcol;

    float acc[8][8];
#pragma unroll
    for (int i = 0; i < 8; i++)
#pragma unroll
        for (int j = 0; j < 8; j++) acc[i][j] = 0.f;

    for (int k0 = 0; k0 < K; k0 += 8) {
        float4 av = *reinterpret_cast<const float4*>(Aptr + k0);
        As[acol + 0][arow] = av.x; As[acol + 1][arow] = av.y;
        As[acol + 2][arow] = av.z; As[acol + 3][arow] = av.w;
        *reinterpret_cast<float4*>(&Bs[brow][bcol]) =
            *reinterpret_cast<const float4*>(Bptr + (size_t)k0 * N);
        __syncthreads();
#pragma unroll
        for (int kk = 0; kk < 8; kk++) {
            float4 a0 = *reinterpret_cast<const float4*>(&As[kk][ty << 2]);
            float4 a1 = *reinterpret_cast<const float4*>(&As[kk][64 + (ty << 2)]);
            float4 b0 = *reinterpret_cast<const float4*>(&Bs[kk][tx << 2]);
            float4 b1 = *reinterpret_cast<const float4*>(&Bs[kk][64 + (tx << 2)]);
            float am[8] = {a0.x, a0.y, a0.z, a0.w, a1.x, a1.y, a1.z, a1.w};
            float bn[8] = {b0.x, b0.y, b0.z, b0.w, b1.x, b1.y, b1.z, b1.w};
#pragma unroll
            for (int i = 0; i < 8; i++)
#pragma unroll
                for (int j = 0; j < 8; j++)
                    acc[i][j] = fmaf(am[i], bn[j], acc[i][j]);
        }
        __syncthreads();
    }

#pragma unroll
    for (int i = 0; i < 8; i++) {
        int m = m0 + (ty << 2) + (i & 3) + ((i >> 2) << 6);
        float bv = bias[m];
#pragma unroll
        for (int jh = 0; jh < 2; jh++) {
            int n = n0 + (tx << 2) + (jh << 6);
            float4 o;
            o.x = acc[i][jh * 4 + 0] + bv;
            o.y = acc[i][jh * 4 + 1] + bv;
            o.z = acc[i][jh * 4 + 2] + bv;
            o.w = acc[i][jh * 4 + 3] + bv;
            if (MODE == 1) {
                float4 rv = *reinterpret_cast<const float4*>(
                    resid + (size_t)blockIdx.z * strideR + (size_t)m * N + n);
                o.x += rv.x; o.y += rv.y; o.z += rv.z; o.w += rv.w;
            }
            *reinterpret_cast<float4*>(Cp + (size_t)m * N + n) = o;
        }
    }
}

// ---------------------------------------------------------------------------
// Flash attention (fp32): one block = one head x 64 query positions.
// ch = 64. Streams K/V in 64-wide s-tiles with online softmax.
// q and k each pre-scaled by 1/sqrt(sqrt(ch)) (matches reference exactly).
// Layouts in smem:
//   Qs [c][i]  (64x64), KVs [c][j] (64x68) holds K then V,
//   Ps [i][j]  raw scores (64x68), PT [j][i] exp-probs (64x68).
// ---------------------------------------------------------------------------
constexpr int ATTN_SMEM = (64 * 64 + 3 * 64 * 68 + 3 * 64 + 256) * 4;  // 70400 B

__global__ void attn_kernel(const float* __restrict__ qkv,
                            float* __restrict__ attn_out) {
    extern __shared__ float sm[];
    float* Qs   = sm;                 // 64*64
    float* KVs  = Qs + 64 * 64;       // 64*68
    float* Ps   = KVs + 64 * 68;      // 64*68
    float* PT   = Ps + 64 * 68;       // 64*68
    float* mrow = PT + 64 * 68;       // 64
    float* lrow = mrow + 64;          // 64
    float* arow = lrow + 64;          // 64
    float* red  = arow + 64;          // 64*4

    const int tid = threadIdx.x;
    const int tx = tid & 15, ty = tid >> 4;
    const int qt0 = blockIdx.x * 64;
    const int b = blockIdx.y / NH, h = blockIdx.y % NH;
    const size_t qbase = ((size_t)b * 3 * NC + (size_t)h * CH) * NT;
    const size_t kbase = qbase + (size_t)NC * NT;
    const size_t vbase = qbase + (size_t)2 * NC * NT;
    const float scale = 0.35355339059327373f;  // 1/sqrt(sqrt(64))

    // Load Q tile (scaled)
#pragma unroll
    for (int l = 0; l < 4; l++) {
        int v = tid + l * 256;
        int c = v >> 4;
        int i4 = (v & 15) << 2;
        float4 q4 = *reinterpret_cast<const float4*>(
            qkv + qbase + (size_t)c * NT + qt0 + i4);
        q4.x *= scale; q4.y *= scale; q4.z *= scale; q4.w *= scale;
        *reinterpret_cast<float4*>(&Qs[c * 64 + i4]) = q4;
    }
    if (tid < 64) { mrow[tid] = -1e30f; lrow[tid] = 0.f; }

    float o_acc[16];
#pragma unroll
    for (int i = 0; i < 16; i++) o_acc[i] = 0.f;

    const int si = tid >> 2;    // softmax: row owned by this thread
    const int sp = tid & 3;     // softmax: 4-way partition of the row
    const int sj0 = sp << 4;

    for (int s0 = 0; s0 < NT; s0 += 64) {
        __syncthreads();  // KVs/PT safe to overwrite; also orders first Q load
        // Load K tile (scaled)
#pragma unroll
        for (int l = 0; l < 4; l++) {
            int v = tid + l * 256;
            int c = v >> 4;
            int j4 = (v & 15) << 2;
            float4 k4 = *reinterpret_cast<const float4*>(
                qkv + kbase + (size_t)c * NT + s0 + j4);
            k4.x *= scale; k4.y *= scale; k4.z *= scale; k4.w *= scale;
            *reinterpret_cast<float4*>(&KVs[c * 68 + j4]) = k4;
        }
        __syncthreads();

        // S[i][j] = sum_c Q[c][i] * K[c][j]; thread owns i0=ty*4, j0=tx*4
        float sacc[16];
#pragma unroll
        for (int i = 0; i < 16; i++) sacc[i] = 0.f;
#pragma unroll 8
        for (int cc = 0; cc < 64; cc++) {
            float4 qv = *reinterpret_cast<const float4*>(&Qs[cc * 64 + (ty << 2)]);
            float4 kv = *reinterpret_cast<const float4*>(&KVs[cc * 68 + (tx << 2)]);
            float qa[4] = {qv.x, qv.y, qv.z, qv.w};
            float ka[4] = {kv.x, kv.y, kv.z, kv.w};
#pragma unroll
            for (int r = 0; r < 4; r++)
#pragma unroll
                for (int q = 0; q < 4; q++)
                    sacc[r * 4 + q] = fmaf(qa[r], ka[q], sacc[r * 4 + q]);
        }
#pragma unroll
        for (int r = 0; r < 4; r++) {
            float4 sv = make_float4(sacc[r * 4 + 0], sacc[r * 4 + 1],
                                    sacc[r * 4 + 2], sacc[r * 4 + 3]);
            *reinterpret_cast<float4*>(&Ps[((ty << 2) + r) * 68 + (tx << 2)]) = sv;
        }
        __syncthreads();

        // Load V tile (overwrites KVs) — overlaps with softmax below
#pragma unroll
        for (int l = 0; l < 4; l++) {
            int v = tid + l * 256;
            int c = v >> 4;
            int j4 = (v & 15) << 2;
            float4 v4 = *reinterpret_cast<const float4*>(
                qkv + vbase + (size_t)c * NT + s0 + j4);
            *reinterpret_cast<float4*>(&KVs[c * 68 + j4]) = v4;
        }

        // Online softmax: step 1 — per-part max
        {
            float lm = -1e30f;
#pragma unroll
            for (int jj = 0; jj < 16; jj++)
                lm = fmaxf(lm, Ps[si * 68 + sj0 + jj]);
            red[si * 4 + sp] = lm;
        }
        __syncthreads();
        if (sp == 0) {
            float m_loc = fmaxf(fmaxf(red[si * 4], red[si * 4 + 1]),
                                fmaxf(red[si * 4 + 2], red[si * 4 + 3]));
            float m_new = fmaxf(mrow[si], m_loc);
            arow[si] = __expf(mrow[si] - m_new);
            mrow[si] = m_new;
        }
        __syncthreads();
        // step 2 — exp, write transposed probs, per-part sum
        {
            float mn = mrow[si];
            float s = 0.f;
#pragma unroll
            for (int jj = 0; jj < 16; jj++) {
                int j = sj0 + jj;
                float e = __expf(Ps[si * 68 + j] - mn);
                PT[j * 68 + si] = e;
                s += e;
            }
            red[si * 4 + sp] = s;
        }
        __syncthreads();
        if (sp == 0) {
            lrow[si] = lrow[si] * arow[si] +
                       red[si * 4] + red[si * 4 + 1] + red[si * 4 + 2] + red[si * 4 + 3];
        }
        __syncthreads();

        // O update: thread owns c0=ty*4, i0=tx*4. O = O*alpha + V @ P^T
        float4 al = *reinterpret_cast<const float4*>(&arow[tx << 2]);
        float aa[4] = {al.x, al.y, al.z, al.w};
#pragma unroll
        for (int r = 0; r < 4; r++)
#pragma unroll
            for (int q = 0; q < 4; q++) o_acc[r * 4 + q] *= aa[q];
#pragma unroll 4
        for (int j = 0; j < 64; j++) {
            float4 pv = *reinterpret_cast<const float4*>(&PT[j * 68 + (tx << 2)]);
            float pa[4] = {pv.x, pv.y, pv.z, pv.w};
            float va[4];
#pragma unroll
            for (int r = 0; r < 4; r++) va[r] = KVs[((ty << 2) + r) * 68 + j];
#pragma unroll
            for (int r = 0; r < 4; r++)
#pragma unroll
                for (int q = 0; q < 4; q++)
                    o_acc[r * 4 + q] = fmaf(va[r], pa[q], o_acc[r * 4 + q]);
        }
    }
    __syncthreads();

    // Epilogue: divide by l, write a[b, h*64+c, qt0+i]
    const size_t abase = ((size_t)b * NC + (size_t)h * CH) * NT;
    float4 lv = *reinterpret_cast<const float4*>(&lrow[tx << 2]);
    float linv[4] = {1.f / lv.x, 1.f / lv.y, 1.f / lv.z, 1.f / lv.w};
#pragma unroll
    for (int r = 0; r < 4; r++) {
        int c = (ty << 2) + r;
        float4 o;
        o.x = o_acc[r * 4 + 0] * linv[0];
        o.y = o_acc[r * 4 + 1] * linv[1];
        o.z = o_acc[r * 4 + 2] * linv[2];
        o.w = o_acc[r * 4 + 3] * linv[3];
        *reinterpret_cast<float4*>(attn_out + abase + (size_t)c * NT + qt0 + (tx << 2)) = o;
    }
}

// ---------------------------------------------------------------------------
extern "C" void kernel_launch(void* const* d_in, const int* in_sizes, int n_in,
                              void* d_out, int out_size) {
    const float* x        = (const float*)d_in[0];
    const float* gn_scale = (const float*)d_in[1];
    const float* gn_bias  = (const float*)d_in[2];
    const float* qkv_w    = (const float*)d_in[3];
    const float* qkv_b    = (const float*)d_in[4];
    const float* proj_w   = (const float*)d_in[5];
    const float* proj_b   = (const float*)d_in[6];
    float* out = (float*)d_out;

    float *xn, *qkvb, *attnb;
    cudaGetSymbolAddress((void**)&xn, g_xn);
    cudaGetSymbolAddress((void**)&qkvb, g_qkv);
    cudaGetSymbolAddress((void**)&attnb, g_attn);

    // 1) GroupNorm
    gn_kernel<<<NB * NG, 512>>>(x, gn_scale, gn_bias, xn);

    // 2) QKV GEMM: [3072x1024] x [1024x2048] per batch (+bias)
    dim3 gq(NT / 128, 3 * NC / 128, NB);
    sgemm128<0><<<gq, 256>>>(qkv_w, xn, qkv_b, nullptr, qkvb,
                             3 * NC, NT, NC,
                             (long)NC * NT, (long)3 * NC * NT, 0L);

    // 3) Flash attention per head
    cudaFuncSetAttribute(attn_kernel,
                         cudaFuncAttributeMaxDynamicSharedMemorySize, ATTN_SMEM);
    attn_kernel<<<dim3(NT / 64, NB * NH), 256, ATTN_SMEM>>>(qkvb, attnb);

    // 4) Proj GEMM + bias + residual -> d_out
    dim3 gp(NT / 128, NC / 128, NB);
    sgemm128<1><<<gp, 256>>>(proj_w, attnb, proj_b, x, out,
                             NC, NT, NC,
                             (long)NC * NT, (long)NC * NT, (long)NC * NT);
}

// round 3
// speedup vs baseline: 1.4189x; 1.4189x over previous
#include <cuda_runtime.h>
#include <cstdint>

constexpr int NB = 4;      // batch
constexpr int NC = 1024;   // channels
constexpr int NT = 2048;   // time
constexpr int NH = 16;     // heads
constexpr int NG = 32;     // groups
constexpr int CPG = NC / NG;   // 32 channels per group
constexpr int CH  = NC / NH;   // 64 channels per head
constexpr float EPS = 1e-5f;

// Scratch (device globals — no allocation inside kernel_launch)
__device__ float g_xn[NB * NC * NT];        // 32 MB
__device__ float g_qkv[NB * 3 * NC * NT];   // 96 MB
__device__ float g_attn[NB * NC * NT];      // 32 MB

__device__ __forceinline__ uint32_t f2tf32(float x) {
    uint32_t r;
    asm("cvt.rna.tf32.f32 %0, %1;" : "=r"(r) : "f"(x));
    return r;
}

__device__ __forceinline__ void mma_tf32(float* c, const uint32_t* a,
                                         const uint32_t* b) {
    asm volatile(
        "mma.sync.aligned.m16n8k8.row.col.f32.tf32.tf32.f32 "
        "{%0,%1,%2,%3}, {%4,%5,%6,%7}, {%8,%9}, {%0,%1,%2,%3};"
        : "+f"(c[0]), "+f"(c[1]), "+f"(c[2]), "+f"(c[3])
        : "r"(a[0]), "r"(a[1]), "r"(a[2]), "r"(a[3]), "r"(b[0]), "r"(b[1]));
}

// ============================================================================
// GroupNorm(32, C): unchanged (validated R1)
// ============================================================================
__global__ void gn_kernel(const float* __restrict__ x,
                          const float* __restrict__ gamma,
                          const float* __restrict__ beta,
                          float* __restrict__ xn) {
    const int b = blockIdx.x / NG;
    const int g = blockIdx.x % NG;
    const int n = CPG * NT;
    const size_t base = ((size_t)b * NC + (size_t)g * CPG) * NT;
    const float4* xv = reinterpret_cast<const float4*>(x + base);
    float4* ov = reinterpret_cast<float4*>(xn + base);
    const int nv = n / 4;

    float s = 0.f, sq = 0.f;
    for (int i = threadIdx.x; i < nv; i += blockDim.x) {
        float4 v = xv[i];
        s  += v.x + v.y + v.z + v.w;
        sq += v.x * v.x + v.y * v.y + v.z * v.z + v.w * v.w;
    }
    __shared__ float ss[512], sq2[512];
    ss[threadIdx.x] = s; sq2[threadIdx.x] = sq;
    __syncthreads();
    for (int o = blockDim.x >> 1; o > 0; o >>= 1) {
        if (threadIdx.x < (unsigned)o) {
            ss[threadIdx.x]  += ss[threadIdx.x + o];
            sq2[threadIdx.x] += sq2[threadIdx.x + o];
        }
        __syncthreads();
    }
    __shared__ float smean, srstd;
    if (threadIdx.x == 0) {
        float m   = ss[0] / n;
        float var = sq2[0] / n - m * m;
        smean = m;
        srstd = rsqrtf(var + EPS);
    }
    __syncthreads();
    const float m = smean, r = srstd;
    for (int i = threadIdx.x; i < nv; i += blockDim.x) {
        int c = g * CPG + (i >> 9);
        float sc = gamma[c] * r;
        float bi = beta[c] - m * sc;
        float4 v = xv[i];
        float4 o;
        o.x = v.x * sc + bi; o.y = v.y * sc + bi;
        o.z = v.z * sc + bi; o.w = v.w * sc + bi;
        ov[i] = o;
    }
}

// ============================================================================
// TF32 mma.sync GEMM: C[z][M,N] = W[M,K] * X[z][K,N] + bias (+resid MODE=1)
// CTA 128x128, BK=32, 256 threads = 8 warps (warp tile 32x64).
// Smem: As[stage][128][36] (m-major rows of k), Bs[stage][128][36] (n rows of
// k, i.e. X transposed on store). Pitch 36 -> conflict-free fragment LDS.
// Double-buffered, register-staged prefetch, one __syncthreads per K-iter.
// N fixed = NT by the launches.
// ============================================================================
constexpr int GP   = 36;                      // smem row pitch (floats)
constexpr int GST  = 128 * GP;                // one tile array (floats)
constexpr int GEMM_SMEM = 2 * 2 * GST * 4;    // 73728 bytes

template <int MODE>
__global__ void __launch_bounds__(256) gemm_mma(
    const float* __restrict__ W, const float* __restrict__ X,
    const float* __restrict__ bias, const float* __restrict__ resid,
    float* __restrict__ C, int K,
    long strideB, long strideC, long strideR) {
    extern __shared__ float sm[];
    // stage s: As = sm + s*2*GST, Bs = sm + s*2*GST + GST

    const int t = threadIdx.x;
    const int wid = t >> 5, lane = t & 31;
    const int gi = lane >> 2, li = lane & 3;
    const int wm0 = (wid & 3) * 32;
    const int wn0 = (wid >> 2) * 64;
    const int m0 = blockIdx.y * 128;
    const int n0 = blockIdx.x * 128;
    const int z  = blockIdx.z;

    // gmem load assignments
    const int arow = t >> 1;                 // 0..127
    const int ac   = (t & 1) * 16;           // k offset 0/16
    const float* Wp = W + (size_t)(m0 + arow) * K + ac;
    const int bn   = t & 127;                // n within tile
    const int bk0  = (t >> 7) * 16;          // k offset 0/16
    const float* Xp = X + (size_t)z * strideB + (size_t)bk0 * NT + n0 + bn;

    float c[2][8][4];
#pragma unroll
    for (int mt = 0; mt < 2; mt++)
#pragma unroll
        for (int nt = 0; nt < 8; nt++)
#pragma unroll
            for (int i = 0; i < 4; i++) c[mt][nt][i] = 0.f;

    float4 apre[4];
    float  bpre[16];
    const int NIT = K / 32;

    // ---- load tile 0 ----
#pragma unroll
    for (int i = 0; i < 4; i++)
        apre[i] = *reinterpret_cast<const float4*>(Wp + i * 4);
#pragma unroll
    for (int j = 0; j < 16; j++)
        bpre[j] = Xp[(size_t)j * NT];
    {
        float* As = sm;
        float* Bs = sm + GST;
#pragma unroll
        for (int i = 0; i < 4; i++) {
            uint4 u = make_uint4(f2tf32(apre[i].x), f2tf32(apre[i].y),
                                 f2tf32(apre[i].z), f2tf32(apre[i].w));
            *reinterpret_cast<uint4*>(&As[arow * GP + ac + i * 4]) = u;
        }
#pragma unroll
        for (int j = 0; j < 4; j++) {
            uint4 u = make_uint4(f2tf32(bpre[j * 4 + 0]), f2tf32(bpre[j * 4 + 1]),
                                 f2tf32(bpre[j * 4 + 2]), f2tf32(bpre[j * 4 + 3]));
            *reinterpret_cast<uint4*>(&Bs[bn * GP + bk0 + j * 4]) = u;
        }
    }
    __syncthreads();

    for (int it = 0; it < NIT; it++) {
        // prefetch next tile into regs
        if (it + 1 < NIT) {
            const int k0 = (it + 1) * 32;
#pragma unroll
            for (int i = 0; i < 4; i++)
                apre[i] = *reinterpret_cast<const float4*>(Wp + k0 + i * 4);
#pragma unroll
            for (int j = 0; j < 16; j++)
                bpre[j] = Xp[(size_t)(k0 + j) * NT];
        }

        // compute on current stage
        const uint32_t* As = reinterpret_cast<const uint32_t*>(sm + (it & 1) * 2 * GST);
        const uint32_t* Bs = As + GST;
#pragma unroll
        for (int ks = 0; ks < 4; ks++) {
            const int k8 = ks * 8;
            uint32_t a[2][4];
#pragma unroll
            for (int mt = 0; mt < 2; mt++) {
                int base = (wm0 + mt * 16 + gi) * GP + k8 + li;
                a[mt][0] = As[base];
                a[mt][1] = As[base + 8 * GP];
                a[mt][2] = As[base + 4];
                a[mt][3] = As[base + 8 * GP + 4];
            }
            uint32_t b[8][2];
#pragma unroll
            for (int nt = 0; nt < 8; nt++) {
                int base = (wn0 + nt * 8 + gi) * GP + k8 + li;
                b[nt][0] = Bs[base];
                b[nt][1] = Bs[base + 4];
            }
#pragma unroll
            for (int mt = 0; mt < 2; mt++)
#pragma unroll
                for (int nt = 0; nt < 8; nt++)
                    mma_tf32(c[mt][nt], a[mt], b[nt]);
        }

        // store next tile to the other stage
        if (it + 1 < NIT) {
            float* Asn = sm + ((it + 1) & 1) * 2 * GST;
            float* Bsn = Asn + GST;
#pragma unroll
            for (int i = 0; i < 4; i++) {
                uint4 u = make_uint4(f2tf32(apre[i].x), f2tf32(apre[i].y),
                                     f2tf32(apre[i].z), f2tf32(apre[i].w));
                *reinterpret_cast<uint4*>(&Asn[arow * GP + ac + i * 4]) = u;
            }
#pragma unroll
            for (int j = 0; j < 4; j++) {
                uint4 u = make_uint4(f2tf32(bpre[j * 4 + 0]), f2tf32(bpre[j * 4 + 1]),
                                     f2tf32(bpre[j * 4 + 2]), f2tf32(bpre[j * 4 + 3]));
                *reinterpret_cast<uint4*>(&Bsn[bn * GP + bk0 + j * 4]) = u;
            }
            __syncthreads();
        }
    }

    // Epilogue: c[mt][nt] rows = wm0+mt*16+gi (+8), cols = wn0+nt*8+2*li (+1)
    float* Cbase = C + (size_t)z * strideC;
    const float* Rbase = (MODE == 1) ? (resid + (size_t)z * strideR) : nullptr;
#pragma unroll
    for (int mt = 0; mt < 2; mt++) {
#pragma unroll
        for (int h = 0; h < 2; h++) {
            const int m = m0 + wm0 + mt * 16 + gi + h * 8;
            const float bv = bias[m];
            float* Cp = Cbase + (size_t)m * NT + n0 + wn0;
            const float* Rp = (MODE == 1) ? (Rbase + (size_t)m * NT + n0 + wn0) : nullptr;
#pragma unroll
            for (int nt = 0; nt < 8; nt++) {
                const int col = nt * 8 + 2 * li;
                float2 o;
                o.x = c[mt][nt][2 * h + 0] + bv;
                o.y = c[mt][nt][2 * h + 1] + bv;
                if (MODE == 1) {
                    float2 rv = *reinterpret_cast<const float2*>(Rp + col);
                    o.x += rv.x; o.y += rv.y;
                }
                *reinterpret_cast<float2*>(Cp + col) = o;
            }
        }
    }
}

// ============================================================================
// Flash attention (fp32 SIMT): unchanged (validated R1)
// ============================================================================
constexpr int ATTN_SMEM = (64 * 64 + 3 * 64 * 68 + 3 * 64 + 256) * 4;

__global__ void attn_kernel(const float* __restrict__ qkv,
                            float* __restrict__ attn_out) {
    extern __shared__ float sm[];
    float* Qs   = sm;
    float* KVs  = Qs + 64 * 64;
    float* Ps   = KVs + 64 * 68;
    float* PT   = Ps + 64 * 68;
    float* mrow = PT + 64 * 68;
    float* lrow = mrow + 64;
    float* arow = lrow + 64;
    float* red  = arow + 64;

    const int tid = threadIdx.x;
    const int tx = tid & 15, ty = tid >> 4;
    const int qt0 = blockIdx.x * 64;
    const int b = blockIdx.y / NH, h = blockIdx.y % NH;
    const size_t qbase = ((size_t)b * 3 * NC + (size_t)h * CH) * NT;
    const size_t kbase = qbase + (size_t)NC * NT;
    const size_t vbase = qbase + (size_t)2 * NC * NT;
    const float scale = 0.35355339059327373f;

#pragma unroll
    for (int l = 0; l < 4; l++) {
        int v = tid + l * 256;
        int c = v >> 4;
        int i4 = (v & 15) << 2;
        float4 q4 = *reinterpret_cast<const float4*>(
            qkv + qbase + (size_t)c * NT + qt0 + i4);
        q4.x *= scale; q4.y *= scale; q4.z *= scale; q4.w *= scale;
        *reinterpret_cast<float4*>(&Qs[c * 64 + i4]) = q4;
    }
    if (tid < 64) { mrow[tid] = -1e30f; lrow[tid] = 0.f; }

    float o_acc[16];
#pragma unroll
    for (int i = 0; i < 16; i++) o_acc[i] = 0.f;

    const int si = tid >> 2;
    const int sp = tid & 3;
    const int sj0 = sp << 4;

    for (int s0 = 0; s0 < NT; s0 += 64) {
        __syncthreads();
#pragma unroll
        for (int l = 0; l < 4; l++) {
            int v = tid + l * 256;
            int c = v >> 4;
            int j4 = (v & 15) << 2;
            float4 k4 = *reinterpret_cast<const float4*>(
                qkv + kbase + (size_t)c * NT + s0 + j4);
            k4.x *= scale; k4.y *= scale; k4.z *= scale; k4.w *= scale;
            *reinterpret_cast<float4*>(&KVs[c * 68 + j4]) = k4;
        }
        __syncthreads();

        float sacc[16];
#pragma unroll
        for (int i = 0; i < 16; i++) sacc[i] = 0.f;
#pragma unroll 8
        for (int cc = 0; cc < 64; cc++) {
            float4 qv = *reinterpret_cast<const float4*>(&Qs[cc * 64 + (ty << 2)]);
            float4 kv = *reinterpret_cast<const float4*>(&KVs[cc * 68 + (tx << 2)]);
            float qa[4] = {qv.x, qv.y, qv.z, qv.w};
            float ka[4] = {kv.x, kv.y, kv.z, kv.w};
#pragma unroll
            for (int r = 0; r < 4; r++)
#pragma unroll
                for (int q = 0; q < 4; q++)
                    sacc[r * 4 + q] = fmaf(qa[r], ka[q], sacc[r * 4 + q]);
        }
#pragma unroll
        for (int r = 0; r < 4; r++) {
            float4 sv = make_float4(sacc[r * 4 + 0], sacc[r * 4 + 1],
                                    sacc[r * 4 + 2], sacc[r * 4 + 3]);
            *reinterpret_cast<float4*>(&Ps[((ty << 2) + r) * 68 + (tx << 2)]) = sv;
        }
        __syncthreads();

#pragma unroll
        for (int l = 0; l < 4; l++) {
            int v = tid + l * 256;
            int c = v >> 4;
            int j4 = (v & 15) << 2;
            float4 v4 = *reinterpret_cast<const float4*>(
                qkv + vbase + (size_t)c * NT + s0 + j4);
            *reinterpret_cast<float4*>(&KVs[c * 68 + j4]) = v4;
        }

        {
            float lm = -1e30f;
#pragma unroll
            for (int jj = 0; jj < 16; jj++)
                lm = fmaxf(lm, Ps[si * 68 + sj0 + jj]);
            red[si * 4 + sp] = lm;
        }
        __syncthreads();
        if (sp == 0) {
            float m_loc = fmaxf(fmaxf(red[si * 4], red[si * 4 + 1]),
                                fmaxf(red[si * 4 + 2], red[si * 4 + 3]));
            float m_new = fmaxf(mrow[si], m_loc);
            arow[si] = __expf(mrow[si] - m_new);
            mrow[si] = m_new;
        }
        __syncthreads();
        {
            float mn = mrow[si];
            float s = 0.f;
#pragma unroll
            for (int jj = 0; jj < 16; jj++) {
                int j = sj0 + jj;
                float e = __expf(Ps[si * 68 + j] - mn);
                PT[j * 68 + si] = e;
                s += e;
            }
            red[si * 4 + sp] = s;
        }
        __syncthreads();
        if (sp == 0) {
            lrow[si] = lrow[si] * arow[si] +
                       red[si * 4] + red[si * 4 + 1] + red[si * 4 + 2] + red[si * 4 + 3];
        }
        __syncthreads();

        float4 al = *reinterpret_cast<const float4*>(&arow[tx << 2]);
        float aa[4] = {al.x, al.y, al.z, al.w};
#pragma unroll
        for (int r = 0; r < 4; r++)
#pragma unroll
            for (int q = 0; q < 4; q++) o_acc[r * 4 + q] *= aa[q];
#pragma unroll 4
        for (int j = 0; j < 64; j++) {
            float4 pv = *reinterpret_cast<const float4*>(&PT[j * 68 + (tx << 2)]);
            float pa[4] = {pv.x, pv.y, pv.z, pv.w};
            float va[4];
#pragma unroll
            for (int r = 0; r < 4; r++) va[r] = KVs[((ty << 2) + r) * 68 + j];
#pragma unroll
            for (int r = 0; r < 4; r++)
#pragma unroll
                for (int q = 0; q < 4; q++)
                    o_acc[r * 4 + q] = fmaf(va[r], pa[q], o_acc[r * 4 + q]);
        }
    }
    __syncthreads();

    const size_t abase = ((size_t)b * NC + (size_t)h * CH) * NT;
    float4 lv = *reinterpret_cast<const float4*>(&lrow[tx << 2]);
    float linv[4] = {1.f / lv.x, 1.f / lv.y, 1.f / lv.z, 1.f / lv.w};
#pragma unroll
    for (int r = 0; r < 4; r++) {
        int c = (ty << 2) + r;
        float4 o;
        o.x = o_acc[r * 4 + 0] * linv[0];
        o.y = o_acc[r * 4 + 1] * linv[1];
        o.z = o_acc[r * 4 + 2] * linv[2];
        o.w = o_acc[r * 4 + 3] * linv[3];
        *reinterpret_cast<float4*>(attn_out + abase + (size_t)c * NT + qt0 + (tx << 2)) = o;
    }
}

// ---------------------------------------------------------------------------
extern "C" void kernel_launch(void* const* d_in, const int* in_sizes, int n_in,
                              void* d_out, int out_size) {
    const float* x        = (const float*)d_in[0];
    const float* gn_scale = (const float*)d_in[1];
    const float* gn_bias  = (const float*)d_in[2];
    const float* qkv_w    = (const float*)d_in[3];
    const float* qkv_b    = (const float*)d_in[4];
    const float* proj_w   = (const float*)d_in[5];
    const float* proj_b   = (const float*)d_in[6];
    float* out = (float*)d_out;

    float *xn, *qkvb, *attnb;
    cudaGetSymbolAddress((void**)&xn, g_xn);
    cudaGetSymbolAddress((void**)&qkvb, g_qkv);
    cudaGetSymbolAddress((void**)&attnb, g_attn);

    // 1) GroupNorm
    gn_kernel<<<NB * NG, 512>>>(x, gn_scale, gn_bias, xn);

    // 2) QKV GEMM (tf32 mma.sync): [3072x1024] x [1024x2048] per batch (+bias)
    cudaFuncSetAttribute(gemm_mma<0>,
                         cudaFuncAttributeMaxDynamicSharedMemorySize, GEMM_SMEM);
    cudaFuncSetAttribute(gemm_mma<1>,
                         cudaFuncAttributeMaxDynamicSharedMemorySize, GEMM_SMEM);
    dim3 gq(NT / 128, 3 * NC / 128, NB);
    gemm_mma<0><<<gq, 256, GEMM_SMEM>>>(qkv_w, xn, qkv_b, nullptr, qkvb,
                                        NC, (long)NC * NT, (long)3 * NC * NT, 0L);

    // 3) Flash attention per head
    cudaFuncSetAttribute(attn_kernel,
                         cudaFuncAttributeMaxDynamicSharedMemorySize, ATTN_SMEM);
    attn_kernel<<<dim3(NT / 64, NB * NH), 256, ATTN_SMEM>>>(qkvb, attnb);

    // 4) Proj GEMM (tf32 mma.sync) + bias + residual -> d_out
    dim3 gp(NT / 128, NC / 128, NB);
    gemm_mma<1><<<gp, 256, GEMM_SMEM>>>(proj_w, attnb, proj_b, x, out,
                                        NC, (long)NC * NT, (long)NC * NT,
                                        (long)NC * NT);
}

// round 4
// speedup vs baseline: 2.1938x; 1.5461x over previous
#include <cuda_runtime.h>
#include <cstdint>

constexpr int NB = 4;      // batch
constexpr int NC = 1024;   // channels
constexpr int NT = 2048;   // time
constexpr int NH = 16;     // heads
constexpr int NG = 32;     // groups
constexpr int CPG = NC / NG;   // 32 channels per group
constexpr int CH  = NC / NH;   // 64 channels per head
constexpr float EPS = 1e-5f;

// Scratch (device globals — no allocation inside kernel_launch)
__device__ float g_xn[NB * NC * NT];        // 32 MB
__device__ float g_qkv[NB * 3 * NC * NT];   // 96 MB
__device__ float g_attn[NB * NC * NT];      // 32 MB

__device__ __forceinline__ uint32_t f2tf32(float x) {
    uint32_t r;
    asm("cvt.rna.tf32.f32 %0, %1;" : "=r"(r) : "f"(x));
    return r;
}

__device__ __forceinline__ void mma_tf32(float* c, const uint32_t* a,
                                         const uint32_t* b) {
    asm volatile(
        "mma.sync.aligned.m16n8k8.row.col.f32.tf32.tf32.f32 "
        "{%0,%1,%2,%3}, {%4,%5,%6,%7}, {%8,%9}, {%0,%1,%2,%3};"
        : "+f"(c[0]), "+f"(c[1]), "+f"(c[2]), "+f"(c[3])
        : "r"(a[0]), "r"(a[1]), "r"(a[2]), "r"(a[3]), "r"(b[0]), "r"(b[1]));
}

// ============================================================================
// GroupNorm(32, C): unchanged (validated R1)
// ============================================================================
__global__ void gn_kernel(const float* __restrict__ x,
                          const float* __restrict__ gamma,
                          const float* __restrict__ beta,
                          float* __restrict__ xn) {
    const int b = blockIdx.x / NG;
    const int g = blockIdx.x % NG;
    const int n = CPG * NT;
    const size_t base = ((size_t)b * NC + (size_t)g * CPG) * NT;
    const float4* xv = reinterpret_cast<const float4*>(x + base);
    float4* ov = reinterpret_cast<float4*>(xn + base);
    const int nv = n / 4;

    float s = 0.f, sq = 0.f;
    for (int i = threadIdx.x; i < nv; i += blockDim.x) {
        float4 v = xv[i];
        s  += v.x + v.y + v.z + v.w;
        sq += v.x * v.x + v.y * v.y + v.z * v.z + v.w * v.w;
    }
    __shared__ float ss[512], sq2[512];
    ss[threadIdx.x] = s; sq2[threadIdx.x] = sq;
    __syncthreads();
    for (int o = blockDim.x >> 1; o > 0; o >>= 1) {
        if (threadIdx.x < (unsigned)o) {
            ss[threadIdx.x]  += ss[threadIdx.x + o];
            sq2[threadIdx.x] += sq2[threadIdx.x + o];
        }
        __syncthreads();
    }
    __shared__ float smean, srstd;
    if (threadIdx.x == 0) {
        float m   = ss[0] / n;
        float var = sq2[0] / n - m * m;
        smean = m;
        srstd = rsqrtf(var + EPS);
    }
    __syncthreads();
    const float m = smean, r = srstd;
    for (int i = threadIdx.x; i < nv; i += blockDim.x) {
        int c = g * CPG + (i >> 9);
        float sc = gamma[c] * r;
        float bi = beta[c] - m * sc;
        float4 v = xv[i];
        float4 o;
        o.x = v.x * sc + bi; o.y = v.y * sc + bi;
        o.z = v.z * sc + bi; o.w = v.w * sc + bi;
        ov[i] = o;
    }
}

// ============================================================================
// TF32 mma.sync GEMM: unchanged (validated R3)
// ============================================================================
constexpr int GP   = 36;
constexpr int GST  = 128 * GP;
constexpr int GEMM_SMEM = 2 * 2 * GST * 4;

template <int MODE>
__global__ void __launch_bounds__(256) gemm_mma(
    const float* __restrict__ W, const float* __restrict__ X,
    const float* __restrict__ bias, const float* __restrict__ resid,
    float* __restrict__ C, int K,
    long strideB, long strideC, long strideR) {
    extern __shared__ float sm[];

    const int t = threadIdx.x;
    const int wid = t >> 5, lane = t & 31;
    const int gi = lane >> 2, li = lane & 3;
    const int wm0 = (wid & 3) * 32;
    const int wn0 = (wid >> 2) * 64;
    const int m0 = blockIdx.y * 128;
    const int n0 = blockIdx.x * 128;
    const int z  = blockIdx.z;

    const int arow = t >> 1;
    const int ac   = (t & 1) * 16;
    const float* Wp = W + (size_t)(m0 + arow) * K + ac;
    const int bn   = t & 127;
    const int bk0  = (t >> 7) * 16;
    const float* Xp = X + (size_t)z * strideB + (size_t)bk0 * NT + n0 + bn;

    float c[2][8][4];
#pragma unroll
    for (int mt = 0; mt < 2; mt++)
#pragma unroll
        for (int nt = 0; nt < 8; nt++)
#pragma unroll
            for (int i = 0; i < 4; i++) c[mt][nt][i] = 0.f;

    float4 apre[4];
    float  bpre[16];
    const int NIT = K / 32;

#pragma unroll
    for (int i = 0; i < 4; i++)
        apre[i] = *reinterpret_cast<const float4*>(Wp + i * 4);
#pragma unroll
    for (int j = 0; j < 16; j++)
        bpre[j] = Xp[(size_t)j * NT];
    {
        float* As = sm;
        float* Bs = sm + GST;
#pragma unroll
        for (int i = 0; i < 4; i++) {
            uint4 u = make_uint4(f2tf32(apre[i].x), f2tf32(apre[i].y),
                                 f2tf32(apre[i].z), f2tf32(apre[i].w));
            *reinterpret_cast<uint4*>(&As[arow * GP + ac + i * 4]) = u;
        }
#pragma unroll
        for (int j = 0; j < 4; j++) {
            uint4 u = make_uint4(f2tf32(bpre[j * 4 + 0]), f2tf32(bpre[j * 4 + 1]),
                                 f2tf32(bpre[j * 4 + 2]), f2tf32(bpre[j * 4 + 3]));
            *reinterpret_cast<uint4*>(&Bs[bn * GP + bk0 + j * 4]) = u;
        }
    }
    __syncthreads();

    for (int it = 0; it < NIT; it++) {
        if (it + 1 < NIT) {
            const int k0 = (it + 1) * 32;
#pragma unroll
            for (int i = 0; i < 4; i++)
                apre[i] = *reinterpret_cast<const float4*>(Wp + k0 + i * 4);
#pragma unroll
            for (int j = 0; j < 16; j++)
                bpre[j] = Xp[(size_t)(k0 + j) * NT];
        }

        const uint32_t* As = reinterpret_cast<const uint32_t*>(sm + (it & 1) * 2 * GST);
        const uint32_t* Bs = As + GST;
#pragma unroll
        for (int ks = 0; ks < 4; ks++) {
            const int k8 = ks * 8;
            uint32_t a[2][4];
#pragma unroll
            for (int mt = 0; mt < 2; mt++) {
                int base = (wm0 + mt * 16 + gi) * GP + k8 + li;
                a[mt][0] = As[base];
                a[mt][1] = As[base + 8 * GP];
                a[mt][2] = As[base + 4];
                a[mt][3] = As[base + 8 * GP + 4];
            }
            uint32_t b[8][2];
#pragma unroll
            for (int nt = 0; nt < 8; nt++) {
                int base = (wn0 + nt * 8 + gi) * GP + k8 + li;
                b[nt][0] = Bs[base];
                b[nt][1] = Bs[base + 4];
            }
#pragma unroll
            for (int mt = 0; mt < 2; mt++)
#pragma unroll
                for (int nt = 0; nt < 8; nt++)
                    mma_tf32(c[mt][nt], a[mt], b[nt]);
        }

        if (it + 1 < NIT) {
            float* Asn = sm + ((it + 1) & 1) * 2 * GST;
            float* Bsn = Asn + GST;
#pragma unroll
            for (int i = 0; i < 4; i++) {
                uint4 u = make_uint4(f2tf32(apre[i].x), f2tf32(apre[i].y),
                                     f2tf32(apre[i].z), f2tf32(apre[i].w));
                *reinterpret_cast<uint4*>(&Asn[arow * GP + ac + i * 4]) = u;
            }
#pragma unroll
            for (int j = 0; j < 4; j++) {
                uint4 u = make_uint4(f2tf32(bpre[j * 4 + 0]), f2tf32(bpre[j * 4 + 1]),
                                     f2tf32(bpre[j * 4 + 2]), f2tf32(bpre[j * 4 + 3]));
                *reinterpret_cast<uint4*>(&Bsn[bn * GP + bk0 + j * 4]) = u;
            }
            __syncthreads();
        }
    }

    float* Cbase = C + (size_t)z * strideC;
    const float* Rbase = (MODE == 1) ? (resid + (size_t)z * strideR) : nullptr;
#pragma unroll
    for (int mt = 0; mt < 2; mt++) {
#pragma unroll
        for (int h = 0; h < 2; h++) {
            const int m = m0 + wm0 + mt * 16 + gi + h * 8;
            const float bv = bias[m];
            float* Cp = Cbase + (size_t)m * NT + n0 + wn0;
            const float* Rp = (MODE == 1) ? (Rbase + (size_t)m * NT + n0 + wn0) : nullptr;
#pragma unroll
            for (int nt = 0; nt < 8; nt++) {
                const int col = nt * 8 + 2 * li;
                float2 o;
                o.x = c[mt][nt][2 * h + 0] + bv;
                o.y = c[mt][nt][2 * h + 1] + bv;
                if (MODE == 1) {
                    float2 rv = *reinterpret_cast<const float2*>(Rp + col);
                    o.x += rv.x; o.y += rv.y;
                }
                *reinterpret_cast<float2*>(Cp + col) = o;
            }
        }
    }
}

// ============================================================================
// Flash attention with tf32 mma.sync.
// Block = (64-query tile, head). 256 threads = 8 warps; warp tile 16x32 for
// both GEMMs (S = Q^T K and O = V P^T).
// Smem (pitch 68, XOR swizzle col^(8*(row&7)) on Qs/Ks/Ps):
//   Qs[i][c], Ks[j][c], Vs[c][j] (no swizzle), Ps[i][j].
// ============================================================================
constexpr int AP = 68;
constexpr int ATT_SMEM = (4 * 64 * AP + 3 * 64 + 256) * 4;   // 71424 B

__global__ void __launch_bounds__(256) attn_mma(const float* __restrict__ qkv,
                                                float* __restrict__ attn_out) {
    extern __shared__ float sm[];
    float* Qs   = sm;
    float* Ks   = Qs + 64 * AP;
    float* Vs   = Ks + 64 * AP;
    float* Ps   = Vs + 64 * AP;
    float* mrow = Ps + 64 * AP;
    float* lrow = mrow + 64;
    float* arow = lrow + 64;
    float* red  = arow + 64;

    const int tid  = threadIdx.x;
    const int wid  = tid >> 5, lane = tid & 31;
    const int gi   = lane >> 2, li = lane & 3;
    const int wm16 = (wid & 3) * 16;   // S: i-tile base; O: c-tile base
    const int wn32 = (wid >> 2) * 32;  // S: j-tile base; O: i-tile base
    const int qt0  = blockIdx.x * 64;
    const int b    = blockIdx.y >> 4, h = blockIdx.y & 15;
    const size_t qbase = ((size_t)b * 3 * NC + (size_t)h * CH) * NT;
    const size_t kbase = qbase + (size_t)NC * NT;
    const size_t vbase = qbase + 2 * (size_t)NC * NT;
    const float scale = 0.35355339059327373f;  // ch^-0.25

    // Load Q transposed: Qs[i][c], swizzled, tf32, pre-scaled
#pragma unroll
    for (int l = 0; l < 4; l++) {
        int idx = tid + 256 * l;
        int ii  = idx & 63;
        int c4  = (idx >> 6) * 4;
        uint4 u;
        u.x = f2tf32(qkv[qbase + (size_t)(c4 + 0) * NT + qt0 + ii] * scale);
        u.y = f2tf32(qkv[qbase + (size_t)(c4 + 1) * NT + qt0 + ii] * scale);
        u.z = f2tf32(qkv[qbase + (size_t)(c4 + 2) * NT + qt0 + ii] * scale);
        u.w = f2tf32(qkv[qbase + (size_t)(c4 + 3) * NT + qt0 + ii] * scale);
        *reinterpret_cast<uint4*>(&Qs[ii * AP + (c4 ^ (8 * (ii & 7)))]) = u;
    }
    if (tid < 64) { mrow[tid] = -1e30f; lrow[tid] = 0.f; }

    float oacc[4][4];
#pragma unroll
    for (int nt = 0; nt < 4; nt++)
#pragma unroll
        for (int i = 0; i < 4; i++) oacc[nt][i] = 0.f;

    const int si  = tid >> 2;        // softmax row
    const int sp  = tid & 3;         // softmax row-part
    const int sj0 = sp * 16;
    const int ssw = 8 * (si & 7);    // row swizzle for softmax

    for (int s0 = 0; s0 < NT; s0 += 64) {
        __syncthreads();
        // Load K transposed: Ks[j][c] (swizzled, scaled)
#pragma unroll
        for (int l = 0; l < 4; l++) {
            int idx = tid + 256 * l;
            int jj  = idx & 63;
            int c4  = (idx >> 6) * 4;
            uint4 u;
            u.x = f2tf32(qkv[kbase + (size_t)(c4 + 0) * NT + s0 + jj] * scale);
            u.y = f2tf32(qkv[kbase + (size_t)(c4 + 1) * NT + s0 + jj] * scale);
            u.z = f2tf32(qkv[kbase + (size_t)(c4 + 2) * NT + s0 + jj] * scale);
            u.w = f2tf32(qkv[kbase + (size_t)(c4 + 3) * NT + s0 + jj] * scale);
            *reinterpret_cast<uint4*>(&Ks[jj * AP + (c4 ^ (8 * (jj & 7)))]) = u;
        }
        // Load V direct: Vs[c][j] (no swizzle)
#pragma unroll
        for (int l = 0; l < 4; l++) {
            int idx = tid + 256 * l;
            int c   = idx >> 4;
            int j4  = (idx & 15) * 4;
            float4 v = *reinterpret_cast<const float4*>(
                &qkv[vbase + (size_t)c * NT + s0 + j4]);
            uint4 u = make_uint4(f2tf32(v.x), f2tf32(v.y), f2tf32(v.z), f2tf32(v.w));
            *reinterpret_cast<uint4*>(&Vs[c * AP + j4]) = u;
        }
        __syncthreads();

        // ---- S = Q^T K : M=i(64), N=j(64), K=c(64) ----
        float sacc[4][4];
#pragma unroll
        for (int nt = 0; nt < 4; nt++)
#pragma unroll
            for (int i = 0; i < 4; i++) sacc[nt][i] = 0.f;
        {
            const uint32_t* Qu = reinterpret_cast<const uint32_t*>(Qs);
            const uint32_t* Ku = reinterpret_cast<const uint32_t*>(Ks);
#pragma unroll
            for (int ks = 0; ks < 8; ks++) {
                const int ca = (ks * 8 + li) ^ (8 * gi);
                uint32_t a[4];
                a[0] = Qu[(wm16 + gi) * AP + ca];
                a[1] = Qu[(wm16 + gi + 8) * AP + ca];
                a[2] = Qu[(wm16 + gi) * AP + ca + 4];
                a[3] = Qu[(wm16 + gi + 8) * AP + ca + 4];
#pragma unroll
                for (int nt = 0; nt < 4; nt++) {
                    const int jr = (wn32 + nt * 8 + gi) * AP;
                    uint32_t bf[2] = {Ku[jr + ca], Ku[jr + ca + 4]};
                    mma_tf32(sacc[nt], a, bf);
                }
            }
        }
        // store S -> Ps (swizzled)
#pragma unroll
        for (int nt = 0; nt < 4; nt++) {
            const int colS = ((wn32 + nt * 8) ^ (8 * gi)) + 2 * li;
            *reinterpret_cast<float2*>(&Ps[(wm16 + gi) * AP + colS]) =
                make_float2(sacc[nt][0], sacc[nt][1]);
            *reinterpret_cast<float2*>(&Ps[(wm16 + gi + 8) * AP + colS]) =
                make_float2(sacc[nt][2], sacc[nt][3]);
        }
        __syncthreads();

        // ---- online softmax on Ps ----
        {
            float lm = -1e30f;
#pragma unroll
            for (int jj = 0; jj < 16; jj++)
                lm = fmaxf(lm, Ps[si * AP + ((sj0 + jj) ^ ssw)]);
            red[si * 4 + sp] = lm;
        }
        __syncthreads();
        if (sp == 0) {
            float ml = fmaxf(fmaxf(red[si * 4], red[si * 4 + 1]),
                             fmaxf(red[si * 4 + 2], red[si * 4 + 3]));
            float mn = fmaxf(mrow[si], ml);
            arow[si] = __expf(mrow[si] - mn);
            mrow[si] = mn;
        }
        __syncthreads();
        {
            const float mn = mrow[si];
            float s = 0.f;
#pragma unroll
            for (int jj = 0; jj < 16; jj++) {
                const int adr = si * AP + ((sj0 + jj) ^ ssw);
                float e = __expf(Ps[adr] - mn);
                float ef = __uint_as_float(f2tf32(e));  // round BEFORE summing
                Ps[adr] = ef;
                s += ef;
            }
            red[si * 4 + sp] = s;
        }
        __syncthreads();
        if (sp == 0) {
            lrow[si] = lrow[si] * arow[si] + red[si * 4] + red[si * 4 + 1] +
                       red[si * 4 + 2] + red[si * 4 + 3];
        }
        __syncthreads();

        // ---- O = V P^T : M=c(64), N=i(64), K=j(64) ----
#pragma unroll
        for (int nt = 0; nt < 4; nt++) {
            const float a0 = arow[wn32 + nt * 8 + 2 * li];
            const float a1 = arow[wn32 + nt * 8 + 2 * li + 1];
            oacc[nt][0] *= a0; oacc[nt][1] *= a1;
            oacc[nt][2] *= a0; oacc[nt][3] *= a1;
        }
        {
            const uint32_t* Vu = reinterpret_cast<const uint32_t*>(Vs);
            const uint32_t* Pu = reinterpret_cast<const uint32_t*>(Ps);
#pragma unroll
            for (int ks = 0; ks < 8; ks++) {
                const int k8 = ks * 8;
                uint32_t a[4];
                a[0] = Vu[(wm16 + gi) * AP + k8 + li];
                a[1] = Vu[(wm16 + gi + 8) * AP + k8 + li];
                a[2] = Vu[(wm16 + gi) * AP + k8 + li + 4];
                a[3] = Vu[(wm16 + gi + 8) * AP + k8 + li + 4];
                const int cb = (k8 + li) ^ (8 * gi);
#pragma unroll
                for (int nt = 0; nt < 4; nt++) {
                    const int ir = (wn32 + nt * 8 + gi) * AP;
                    uint32_t bf[2] = {Pu[ir + cb], Pu[ir + cb + 4]};
                    mma_tf32(oacc[nt], a, bf);
                }
            }
        }
    }

    // Epilogue: O[c][i] /= l[i]
    const size_t abase = ((size_t)b * NC + (size_t)h * CH) * NT;
#pragma unroll
    for (int nt = 0; nt < 4; nt++) {
        const int i = wn32 + nt * 8 + 2 * li;
        const float l0 = 1.f / lrow[i];
        const float l1 = 1.f / lrow[i + 1];
        *reinterpret_cast<float2*>(
            &attn_out[abase + (size_t)(wm16 + gi) * NT + qt0 + i]) =
            make_float2(oacc[nt][0] * l0, oacc[nt][1] * l1);
        *reinterpret_cast<float2*>(
            &attn_out[abase + (size_t)(wm16 + gi + 8) * NT + qt0 + i]) =
            make_float2(oacc[nt][2] * l0, oacc[nt][3] * l1);
    }
}

// ---------------------------------------------------------------------------
extern "C" void kernel_launch(void* const* d_in, const int* in_sizes, int n_in,
                              void* d_out, int out_size) {
    const float* x        = (const float*)d_in[0];
    const float* gn_scale = (const float*)d_in[1];
    const float* gn_bias  = (const float*)d_in[2];
    const float* qkv_w    = (const float*)d_in[3];
    const float* qkv_b    = (const float*)d_in[4];
    const float* proj_w   = (const float*)d_in[5];
    const float* proj_b   = (const float*)d_in[6];
    float* out = (float*)d_out;

    float *xn, *qkvb, *attnb;
    cudaGetSymbolAddress((void**)&xn, g_xn);
    cudaGetSymbolAddress((void**)&qkvb, g_qkv);
    cudaGetSymbolAddress((void**)&attnb, g_attn);

    // 1) GroupNorm
    gn_kernel<<<NB * NG, 512>>>(x, gn_scale, gn_bias, xn);

    // 2) QKV GEMM (tf32 mma.sync)
    cudaFuncSetAttribute(gemm_mma<0>,
                         cudaFuncAttributeMaxDynamicSharedMemorySize, GEMM_SMEM);
    cudaFuncSetAttribute(gemm_mma<1>,
                         cudaFuncAttributeMaxDynamicSharedMemorySize, GEMM_SMEM);
    dim3 gq(NT / 128, 3 * NC / 128, NB);
    gemm_mma<0><<<gq, 256, GEMM_SMEM>>>(qkv_w, xn, qkv_b, nullptr, qkvb,
                                        NC, (long)NC * NT, (long)3 * NC * NT, 0L);

    // 3) Flash attention (tf32 mma.sync)
    cudaFuncSetAttribute(attn_mma,
                         cudaFuncAttributeMaxDynamicSharedMemorySize, ATT_SMEM);
    attn_mma<<<dim3(NT / 64, NB * NH), 256, ATT_SMEM>>>(qkvb, attnb);

    // 4) Proj GEMM (tf32 mma.sync) + bias + residual -> d_out
    dim3 gp(NT / 128, NC / 128, NB);
    gemm_mma<1><<<gp, 256, GEMM_SMEM>>>(proj_w, attnb, proj_b, x, out,
                                        NC, (long)NC * NT, (long)NC * NT,
                                        (long)NC * NT);
}

// round 5
// speedup vs baseline: 3.2157x; 1.4658x over previous
#include <cuda_runtime.h>
#include <cstdint>

constexpr int NB = 4;      // batch
constexpr int NC = 1024;   // channels
constexpr int NT = 2048;   // time
constexpr int NH = 16;     // heads
constexpr int NG = 32;     // groups
constexpr int CPG = NC / NG;   // 32 channels per group
constexpr int CH  = NC / NH;   // 64 channels per head
constexpr float EPS = 1e-5f;

// Scratch (device globals — no allocation inside kernel_launch)
__device__ float g_xn[NB * NC * NT];        // 32 MB
__device__ float g_qkv[NB * 3 * NC * NT];   // 96 MB
__device__ float g_attn[NB * NC * NT];      // 32 MB

// pack two floats -> bf16x2 (lo = first arg, hi = second arg)
__device__ __forceinline__ uint32_t packbf(float lo, float hi) {
    uint32_t r;
    asm("cvt.rn.bf16x2.f32 %0, %1, %2;" : "=r"(r) : "f"(hi), "f"(lo));
    return r;
}

__device__ __forceinline__ void mma_bf16(float* c, const uint32_t* a,
                                         const uint32_t* b) {
    asm volatile(
        "mma.sync.aligned.m16n8k16.row.col.f32.bf16.bf16.f32 "
        "{%0,%1,%2,%3}, {%4,%5,%6,%7}, {%8,%9}, {%0,%1,%2,%3};"
        : "+f"(c[0]), "+f"(c[1]), "+f"(c[2]), "+f"(c[3])
        : "r"(a[0]), "r"(a[1]), "r"(a[2]), "r"(a[3]), "r"(b[0]), "r"(b[1]));
}

// ============================================================================
// GroupNorm(32, C): unchanged (validated R1)
// ============================================================================
__global__ void gn_kernel(const float* __restrict__ x,
                          const float* __restrict__ gamma,
                          const float* __restrict__ beta,
                          float* __restrict__ xn) {
    const int b = blockIdx.x / NG;
    const int g = blockIdx.x % NG;
    const int n = CPG * NT;
    const size_t base = ((size_t)b * NC + (size_t)g * CPG) * NT;
    const float4* xv = reinterpret_cast<const float4*>(x + base);
    float4* ov = reinterpret_cast<float4*>(xn + base);
    const int nv = n / 4;

    float s = 0.f, sq = 0.f;
    for (int i = threadIdx.x; i < nv; i += blockDim.x) {
        float4 v = xv[i];
        s  += v.x + v.y + v.z + v.w;
        sq += v.x * v.x + v.y * v.y + v.z * v.z + v.w * v.w;
    }
    __shared__ float ss[512], sq2[512];
    ss[threadIdx.x] = s; sq2[threadIdx.x] = sq;
    __syncthreads();
    for (int o = blockDim.x >> 1; o > 0; o >>= 1) {
        if (threadIdx.x < (unsigned)o) {
            ss[threadIdx.x]  += ss[threadIdx.x + o];
            sq2[threadIdx.x] += sq2[threadIdx.x + o];
        }
        __syncthreads();
    }
    __shared__ float smean, srstd;
    if (threadIdx.x == 0) {
        float m   = ss[0] / n;
        float var = sq2[0] / n - m * m;
        smean = m;
        srstd = rsqrtf(var + EPS);
    }
    __syncthreads();
    const float m = smean, r = srstd;
    for (int i = threadIdx.x; i < nv; i += blockDim.x) {
        int c = g * CPG + (i >> 9);
        float sc = gamma[c] * r;
        float bi = beta[c] - m * sc;
        float4 v = xv[i];
        float4 o;
        o.x = v.x * sc + bi; o.y = v.y * sc + bi;
        o.z = v.z * sc + bi; o.w = v.w * sc + bi;
        ov[i] = o;
    }
}

// ============================================================================
// BF16 mma.sync GEMM: C[z][M,N] = W[M,K] * X[z][K,N] + bias (+resid MODE=1)
// CTA 128x128, BK=32, 256 threads, 8 warps (warp tile 32x64).
// Smem tiles bf16: As[128][20u] (m rows of k-pairs), Bs[128][20u] (n rows of
// k-pairs, X transposed on store). uint pitch 20 -> conflict-free LDS.
// Double-buffered, register-staged prefetch, one barrier per K-iter.
// ============================================================================
constexpr int GPU_ = 20;                      // uint pitch
constexpr int GSTG = 128 * GPU_;              // one tile (uints) = 2560
constexpr int GEMM_SMEM = 2 * 2 * GSTG * 4;   // 40960 bytes

template <int MODE>
__global__ void __launch_bounds__(256) gemm_mma(
    const float* __restrict__ W, const float* __restrict__ X,
    const float* __restrict__ bias, const float* __restrict__ resid,
    float* __restrict__ C, int K,
    long strideB, long strideC, long strideR) {
    extern __shared__ uint32_t smu[];
    // stage s: As = smu + s*2*GSTG, Bs = As + GSTG

    const int t = threadIdx.x;
    const int wid = t >> 5, lane = t & 31;
    const int gi = lane >> 2, li = lane & 3;
    const int wm0 = (wid & 3) * 32;
    const int wn0 = (wid >> 2) * 64;
    const int m0 = blockIdx.y * 128;
    const int n0 = blockIdx.x * 128;
    const int z  = blockIdx.z;

    const int arow = t >> 1;
    const int acu  = (t & 1) * 8;            // uint offset within 16-uint row
    const float* Wp = W + (size_t)(m0 + arow) * K + (t & 1) * 16;
    const int bn   = t & 127;
    const int bku  = (t >> 7) * 8;
    const float* Xp = X + (size_t)z * strideB + (size_t)((t >> 7) * 16) * NT + n0 + bn;

    float c[2][8][4];
#pragma unroll
    for (int mt = 0; mt < 2; mt++)
#pragma unroll
        for (int nt = 0; nt < 8; nt++)
#pragma unroll
            for (int i = 0; i < 4; i++) c[mt][nt][i] = 0.f;

    float4 apre[4];
    float  bpre[16];
    const int NIT = K / 32;

#pragma unroll
    for (int i = 0; i < 4; i++)
        apre[i] = *reinterpret_cast<const float4*>(Wp + i * 4);
#pragma unroll
    for (int j = 0; j < 16; j++)
        bpre[j] = Xp[(size_t)j * NT];
    {
        uint32_t* As = smu;
        uint32_t* Bs = smu + GSTG;
        uint32_t ua[8], ub[8];
#pragma unroll
        for (int i = 0; i < 4; i++) {
            ua[2 * i]     = packbf(apre[i].x, apre[i].y);
            ua[2 * i + 1] = packbf(apre[i].z, apre[i].w);
        }
#pragma unroll
        for (int j = 0; j < 8; j++) ub[j] = packbf(bpre[2 * j], bpre[2 * j + 1]);
        *reinterpret_cast<uint4*>(&As[arow * GPU_ + acu])     = *reinterpret_cast<uint4*>(&ua[0]);
        *reinterpret_cast<uint4*>(&As[arow * GPU_ + acu + 4]) = *reinterpret_cast<uint4*>(&ua[4]);
        *reinterpret_cast<uint4*>(&Bs[bn * GPU_ + bku])       = *reinterpret_cast<uint4*>(&ub[0]);
        *reinterpret_cast<uint4*>(&Bs[bn * GPU_ + bku + 4])   = *reinterpret_cast<uint4*>(&ub[4]);
    }
    __syncthreads();

    for (int it = 0; it < NIT; it++) {
        if (it + 1 < NIT) {
            const int k0 = (it + 1) * 32;
#pragma unroll
            for (int i = 0; i < 4; i++)
                apre[i] = *reinterpret_cast<const float4*>(Wp + k0 + i * 4);
#pragma unroll
            for (int j = 0; j < 16; j++)
                bpre[j] = Xp[(size_t)(k0 + j) * NT];
        }

        const uint32_t* As = smu + (it & 1) * 2 * GSTG;
        const uint32_t* Bs = As + GSTG;
#pragma unroll
        for (int ks = 0; ks < 2; ks++) {
            const int ku = ks * 8;
            uint32_t a[2][4];
#pragma unroll
            for (int mt = 0; mt < 2; mt++) {
                int base = (wm0 + mt * 16 + gi) * GPU_ + ku + li;
                a[mt][0] = As[base];
                a[mt][1] = As[base + 8 * GPU_];
                a[mt][2] = As[base + 4];
                a[mt][3] = As[base + 8 * GPU_ + 4];
            }
            uint32_t b[8][2];
#pragma unroll
            for (int nt = 0; nt < 8; nt++) {
                int base = (wn0 + nt * 8 + gi) * GPU_ + ku + li;
                b[nt][0] = Bs[base];
                b[nt][1] = Bs[base + 4];
            }
#pragma unroll
            for (int mt = 0; mt < 2; mt++)
#pragma unroll
                for (int nt = 0; nt < 8; nt++)
                    mma_bf16(c[mt][nt], a[mt], b[nt]);
        }

        if (it + 1 < NIT) {
            uint32_t* Asn = smu + ((it + 1) & 1) * 2 * GSTG;
            uint32_t* Bsn = Asn + GSTG;
            uint32_t ua[8], ub[8];
#pragma unroll
            for (int i = 0; i < 4; i++) {
                ua[2 * i]     = packbf(apre[i].x, apre[i].y);
                ua[2 * i + 1] = packbf(apre[i].z, apre[i].w);
            }
#pragma unroll
            for (int j = 0; j < 8; j++) ub[j] = packbf(bpre[2 * j], bpre[2 * j + 1]);
            *reinterpret_cast<uint4*>(&Asn[arow * GPU_ + acu])     = *reinterpret_cast<uint4*>(&ua[0]);
            *reinterpret_cast<uint4*>(&Asn[arow * GPU_ + acu + 4]) = *reinterpret_cast<uint4*>(&ua[4]);
            *reinterpret_cast<uint4*>(&Bsn[bn * GPU_ + bku])       = *reinterpret_cast<uint4*>(&ub[0]);
            *reinterpret_cast<uint4*>(&Bsn[bn * GPU_ + bku + 4])   = *reinterpret_cast<uint4*>(&ub[4]);
            __syncthreads();
        }
    }

    float* Cbase = C + (size_t)z * strideC;
    const float* Rbase = (MODE == 1) ? (resid + (size_t)z * strideR) : nullptr;
#pragma unroll
    for (int mt = 0; mt < 2; mt++) {
#pragma unroll
        for (int h = 0; h < 2; h++) {
            const int m = m0 + wm0 + mt * 16 + gi + h * 8;
            const float bv = bias[m];
            float* Cp = Cbase + (size_t)m * NT + n0 + wn0;
            const float* Rp = (MODE == 1) ? (Rbase + (size_t)m * NT + n0 + wn0) : nullptr;
#pragma unroll
            for (int nt = 0; nt < 8; nt++) {
                const int col = nt * 8 + 2 * li;
                float2 o;
                o.x = c[mt][nt][2 * h + 0] + bv;
                o.y = c[mt][nt][2 * h + 1] + bv;
                if (MODE == 1) {
                    float2 rv = *reinterpret_cast<const float2*>(Rp + col);
                    o.x += rv.x; o.y += rv.y;
                }
                *reinterpret_cast<float2*>(Cp + col) = o;
            }
        }
    }
}

// ============================================================================
// Flash attention, bf16 mma.sync (m16n8k16).
// Block = (64-query tile, head). 256 threads / 8 warps; warp tile 16x32 for
// both GEMMs (S = Q^T K and O = V P^T).
// bf16 smem (uint pitch 36): Qs[i][c], Ks[j][c], Vs[c][j], Pb[i][j].
// fp32 scores: Ps[i][j] pitch 68 with XOR swizzle (validated R4 layout).
// ============================================================================
constexpr int APU = 36;                        // uint pitch (bf16 tiles)
constexpr int ATU = 64 * APU;                  // 2304 uints per tile
constexpr int ATT_SMEM = (4 * ATU + 64 * 68 + 3 * 64 + 256) * 4;  // 56064 B

__global__ void __launch_bounds__(256) attn_mma(const float* __restrict__ qkv,
                                                float* __restrict__ attn_out) {
    extern __shared__ float sm[];
    uint32_t* Qu = reinterpret_cast<uint32_t*>(sm);
    uint32_t* Ku = Qu + ATU;
    uint32_t* Vu = Ku + ATU;
    uint32_t* Pu = Vu + ATU;
    float* Ps   = sm + 4 * ATU;
    float* mrow = Ps + 64 * 68;
    float* lrow = mrow + 64;
    float* arow = lrow + 64;
    float* red  = arow + 64;

    const int tid  = threadIdx.x;
    const int wid  = tid >> 5, lane = tid & 31;
    const int gi   = lane >> 2, li = lane & 3;
    const int wm16 = (wid & 3) * 16;   // S: i-tile base; O: c-tile base
    const int wn32 = (wid >> 2) * 32;  // S: j-tile base; O: i-tile base
    const int qt0  = blockIdx.x * 64;
    const int b    = blockIdx.y >> 4, h = blockIdx.y & 15;
    const size_t qbase = ((size_t)b * 3 * NC + (size_t)h * CH) * NT;
    const size_t kbase = qbase + (size_t)NC * NT;
    const size_t vbase = qbase + 2 * (size_t)NC * NT;
    const float scale = 0.35355339059327373f;  // ch^-0.25

    // Load Q transposed: Qs[i][c] bf16, pre-scaled
#pragma unroll
    for (int l = 0; l < 4; l++) {
        int idx = tid + 256 * l;
        int ii  = idx & 63;
        int c4  = (idx >> 6) * 4;
        float q0 = qkv[qbase + (size_t)(c4 + 0) * NT + qt0 + ii] * scale;
        float q1 = qkv[qbase + (size_t)(c4 + 1) * NT + qt0 + ii] * scale;
        float q2 = qkv[qbase + (size_t)(c4 + 2) * NT + qt0 + ii] * scale;
        float q3 = qkv[qbase + (size_t)(c4 + 3) * NT + qt0 + ii] * scale;
        uint2 u = make_uint2(packbf(q0, q1), packbf(q2, q3));
        *reinterpret_cast<uint2*>(&Qu[ii * APU + (c4 >> 1)]) = u;
    }
    if (tid < 64) { mrow[tid] = -1e30f; lrow[tid] = 0.f; }

    float oacc[4][4];
#pragma unroll
    for (int nt = 0; nt < 4; nt++)
#pragma unroll
        for (int i = 0; i < 4; i++) oacc[nt][i] = 0.f;

    const int si  = tid >> 2;        // softmax row
    const int sp  = tid & 3;         // softmax row-part
    const int sj0 = sp * 16;
    const int ssw = 8 * (si & 7);    // row swizzle (Ps only)

    for (int s0 = 0; s0 < NT; s0 += 64) {
        __syncthreads();
        // K transposed: Ks[j][c] bf16 (scaled)
#pragma unroll
        for (int l = 0; l < 4; l++) {
            int idx = tid + 256 * l;
            int jj  = idx & 63;
            int c4  = (idx >> 6) * 4;
            float k0 = qkv[kbase + (size_t)(c4 + 0) * NT + s0 + jj] * scale;
            float k1 = qkv[kbase + (size_t)(c4 + 1) * NT + s0 + jj] * scale;
            float k2 = qkv[kbase + (size_t)(c4 + 2) * NT + s0 + jj] * scale;
            float k3 = qkv[kbase + (size_t)(c4 + 3) * NT + s0 + jj] * scale;
            uint2 u = make_uint2(packbf(k0, k1), packbf(k2, k3));
            *reinterpret_cast<uint2*>(&Ku[jj * APU + (c4 >> 1)]) = u;
        }
        // V direct: Vs[c][j] bf16
#pragma unroll
        for (int l = 0; l < 4; l++) {
            int idx = tid + 256 * l;
            int c   = idx >> 4;
            int j4  = (idx & 15) * 4;
            float4 v = *reinterpret_cast<const float4*>(
                &qkv[vbase + (size_t)c * NT + s0 + j4]);
            uint2 u = make_uint2(packbf(v.x, v.y), packbf(v.z, v.w));
            *reinterpret_cast<uint2*>(&Vu[c * APU + (j4 >> 1)]) = u;
        }
        __syncthreads();

        // ---- S = Q^T K : M=i(64), N=j(64), K=c(64) ----
        float sacc[4][4];
#pragma unroll
        for (int nt = 0; nt < 4; nt++)
#pragma unroll
            for (int i = 0; i < 4; i++) sacc[nt][i] = 0.f;
#pragma unroll
        for (int ks = 0; ks < 4; ks++) {
            const int ku = ks * 8;
            uint32_t a[4];
            const int ra = (wm16 + gi) * APU + ku + li;
            a[0] = Qu[ra];
            a[1] = Qu[ra + 8 * APU];
            a[2] = Qu[ra + 4];
            a[3] = Qu[ra + 8 * APU + 4];
#pragma unroll
            for (int nt = 0; nt < 4; nt++) {
                const int rb = (wn32 + nt * 8 + gi) * APU + ku + li;
                uint32_t bf[2] = {Ku[rb], Ku[rb + 4]};
                mma_bf16(sacc[nt], a, bf);
            }
        }
        // store S -> Ps (fp32, swizzled)
#pragma unroll
        for (int nt = 0; nt < 4; nt++) {
            const int colS = ((wn32 + nt * 8) ^ (8 * gi)) + 2 * li;
            *reinterpret_cast<float2*>(&Ps[(wm16 + gi) * 68 + colS]) =
                make_float2(sacc[nt][0], sacc[nt][1]);
            *reinterpret_cast<float2*>(&Ps[(wm16 + gi + 8) * 68 + colS]) =
                make_float2(sacc[nt][2], sacc[nt][3]);
        }
        __syncthreads();

        // ---- online softmax ----
        {
            float lm = -1e30f;
#pragma unroll
            for (int jj = 0; jj < 16; jj++)
                lm = fmaxf(lm, Ps[si * 68 + ((sj0 + jj) ^ ssw)]);
            red[si * 4 + sp] = lm;
        }
        __syncthreads();
        if (sp == 0) {
            float ml = fmaxf(fmaxf(red[si * 4], red[si * 4 + 1]),
                             fmaxf(red[si * 4 + 2], red[si * 4 + 3]));
            float mn = fmaxf(mrow[si], ml);
            arow[si] = __expf(mrow[si] - mn);
            mrow[si] = mn;
        }
        __syncthreads();
        {
            const float mn = mrow[si];
            float s = 0.f;
#pragma unroll
            for (int j2 = 0; j2 < 8; j2++) {
                const int j0 = sj0 + 2 * j2;
                const int adr = si * 68 + (j0 ^ ssw);   // j0 even, ssw mult of 8
                float e0 = __expf(Ps[adr] - mn);
                float e1 = __expf(Ps[adr + 1] - mn);
                uint32_t p = packbf(e0, e1);            // bf16-rounded probs
                s += __uint_as_float(p << 16) +
                     __uint_as_float(p & 0xFFFF0000u);  // sum AFTER rounding
                Pu[si * APU + sp * 8 + j2] = p;
            }
            red[si * 4 + sp] = s;
        }
        __syncthreads();
        if (sp == 0) {
            lrow[si] = lrow[si] * arow[si] + red[si * 4] + red[si * 4 + 1] +
                       red[si * 4 + 2] + red[si * 4 + 3];
        }
        __syncthreads();

        // ---- O = V P^T : M=c(64), N=i(64), K=j(64) ----
#pragma unroll
        for (int nt = 0; nt < 4; nt++) {
            const float a0 = arow[wn32 + nt * 8 + 2 * li];
            const float a1 = arow[wn32 + nt * 8 + 2 * li + 1];
            oacc[nt][0] *= a0; oacc[nt][1] *= a1;
            oacc[nt][2] *= a0; oacc[nt][3] *= a1;
        }
#pragma unroll
        for (int ks = 0; ks < 4; ks++) {
            const int ku = ks * 8;
            uint32_t a[4];
            const int ra = (wm16 + gi) * APU + ku + li;
            a[0] = Vu[ra];
            a[1] = Vu[ra + 8 * APU];
            a[2] = Vu[ra + 4];
            a[3] = Vu[ra + 8 * APU + 4];
#pragma unroll
            for (int nt = 0; nt < 4; nt++) {
                const int rb = (wn32 + nt * 8 + gi) * APU + ku + li;
                uint32_t bf[2] = {Pu[rb], Pu[rb + 4]};
                mma_bf16(oacc[nt], a, bf);
            }
        }
    }
    __syncthreads();

    // Epilogue: O[c][i] /= l[i]
    const size_t abase = ((size_t)b * NC + (size_t)h * CH) * NT;
#pragma unroll
    for (int nt = 0; nt < 4; nt++) {
        const int i = wn32 + nt * 8 + 2 * li;
        const float l0 = 1.f / lrow[i];
        const float l1 = 1.f / lrow[i + 1];
        *reinterpret_cast<float2*>(
            &attn_out[abase + (size_t)(wm16 + gi) * NT + qt0 + i]) =
            make_float2(oacc[nt][0] * l0, oacc[nt][1] * l1);
        *reinterpret_cast<float2*>(
            &attn_out[abase + (size_t)(wm16 + gi + 8) * NT + qt0 + i]) =
            make_float2(oacc[nt][2] * l0, oacc[nt][3] * l1);
    }
}

// ---------------------------------------------------------------------------
extern "C" void kernel_launch(void* const* d_in, const int* in_sizes, int n_in,
                              void* d_out, int out_size) {
    const float* x        = (const float*)d_in[0];
    const float* gn_scale = (const float*)d_in[1];
    const float* gn_bias  = (const float*)d_in[2];
    const float* qkv_w    = (const float*)d_in[3];
    const float* qkv_b    = (const float*)d_in[4];
    const float* proj_w   = (const float*)d_in[5];
    const float* proj_b   = (const float*)d_in[6];
    float* out = (float*)d_out;

    float *xn, *qkvb, *attnb;
    cudaGetSymbolAddress((void**)&xn, g_xn);
    cudaGetSymbolAddress((void**)&qkvb, g_qkv);
    cudaGetSymbolAddress((void**)&attnb, g_attn);

    // 1) GroupNorm
    gn_kernel<<<NB * NG, 512>>>(x, gn_scale, gn_bias, xn);

    // 2) QKV GEMM (bf16 mma.sync)
    cudaFuncSetAttribute(gemm_mma<0>,
                         cudaFuncAttributeMaxDynamicSharedMemorySize, GEMM_SMEM);
    cudaFuncSetAttribute(gemm_mma<1>,
                         cudaFuncAttributeMaxDynamicSharedMemorySize, GEMM_SMEM);
    dim3 gq(NT / 128, 3 * NC / 128, NB);
    gemm_mma<0><<<gq, 256, GEMM_SMEM>>>(qkv_w, xn, qkv_b, nullptr, qkvb,
                                        NC, (long)NC * NT, (long)3 * NC * NT, 0L);

    // 3) Flash attention (bf16 mma.sync)
    cudaFuncSetAttribute(attn_mma,
                         cudaFuncAttributeMaxDynamicSharedMemorySize, ATT_SMEM);
    attn_mma<<<dim3(NT / 64, NB * NH), 256, ATT_SMEM>>>(qkvb, attnb);

    // 4) Proj GEMM (bf16 mma.sync) + bias + residual -> d_out
    dim3 gp(NT / 128, NC / 128, NB);
    gemm_mma<1><<<gp, 256, GEMM_SMEM>>>(proj_w, attnb, proj_b, x, out,
                                        NC, (long)NC * NT, (long)NC * NT,
                                        (long)NC * NT);
}

// round 6
// speedup vs baseline: 4.4525x; 1.3846x over previous
#include <cuda_runtime.h>
#include <cstdint>

constexpr int NB = 4;      // batch
constexpr int NC = 1024;   // channels
constexpr int NT = 2048;   // time
constexpr int NH = 16;     // heads
constexpr int NG = 32;     // groups
constexpr int CPG = NC / NG;   // 32 channels per group
constexpr int CH  = NC / NH;   // 64 channels per head
constexpr float EPS = 1e-5f;

// Scratch (device globals) — bf16 stored as uint16_t
__device__ uint16_t g_xnb [NB * NC * NT];        // 16 MB
__device__ uint16_t g_qkvb[NB * 3 * NC * NT];    // 48 MB
__device__ uint16_t g_attnb[NB * NC * NT];       // 16 MB
__device__ uint16_t g_wqb [3 * NC * NC];         // 6 MB
__device__ uint16_t g_wpb [NC * NC];             // 2 MB

// pack two floats -> bf16x2 (lo = first arg, hi = second arg)
__device__ __forceinline__ uint32_t packbf(float lo, float hi) {
    uint32_t r;
    asm("cvt.rn.bf16x2.f32 %0, %1, %2;" : "=r"(r) : "f"(hi), "f"(lo));
    return r;
}

__device__ __forceinline__ void mma_bf16(float* c, const uint32_t* a,
                                         const uint32_t* b) {
    asm volatile(
        "mma.sync.aligned.m16n8k16.row.col.f32.bf16.bf16.f32 "
        "{%0,%1,%2,%3}, {%4,%5,%6,%7}, {%8,%9}, {%0,%1,%2,%3};"
        : "+f"(c[0]), "+f"(c[1]), "+f"(c[2]), "+f"(c[3])
        : "r"(a[0]), "r"(a[1]), "r"(a[2]), "r"(a[3]), "r"(b[0]), "r"(b[1]));
}

// ============================================================================
// Weight conversion fp32 -> bf16 (once per launch, deterministic)
// ============================================================================
__global__ void wconv(const float* __restrict__ W, uint16_t* __restrict__ Wb,
                      int n) {
    int i = (blockIdx.x * blockDim.x + threadIdx.x) * 4;
    if (i < n) {
        float4 v = *reinterpret_cast<const float4*>(W + i);
        uint2 u = make_uint2(packbf(v.x, v.y), packbf(v.z, v.w));
        *reinterpret_cast<uint2*>(Wb + i) = u;
    }
}

// ============================================================================
// GroupNorm(32, C) -> bf16 output
// ============================================================================
__global__ void gn_kernel(const float* __restrict__ x,
                          const float* __restrict__ gamma,
                          const float* __restrict__ beta,
                          uint16_t* __restrict__ xnb) {
    const int b = blockIdx.x / NG;
    const int g = blockIdx.x % NG;
    const int n = CPG * NT;
    const size_t base = ((size_t)b * NC + (size_t)g * CPG) * NT;
    const float4* xv = reinterpret_cast<const float4*>(x + base);
    const int nv = n / 4;

    float s = 0.f, sq = 0.f;
    for (int i = threadIdx.x; i < nv; i += blockDim.x) {
        float4 v = xv[i];
        s  += v.x + v.y + v.z + v.w;
        sq += v.x * v.x + v.y * v.y + v.z * v.z + v.w * v.w;
    }
    __shared__ float ss[512], sq2[512];
    ss[threadIdx.x] = s; sq2[threadIdx.x] = sq;
    __syncthreads();
    for (int o = blockDim.x >> 1; o > 0; o >>= 1) {
        if (threadIdx.x < (unsigned)o) {
            ss[threadIdx.x]  += ss[threadIdx.x + o];
            sq2[threadIdx.x] += sq2[threadIdx.x + o];
        }
        __syncthreads();
    }
    __shared__ float smean, srstd;
    if (threadIdx.x == 0) {
        float m   = ss[0] / n;
        float var = sq2[0] / n - m * m;
        smean = m;
        srstd = rsqrtf(var + EPS);
    }
    __syncthreads();
    const float m = smean, r = srstd;
    for (int i = threadIdx.x; i < nv; i += blockDim.x) {
        int c = g * CPG + (i >> 9);
        float sc = gamma[c] * r;
        float bi = beta[c] - m * sc;
        float4 v = xv[i];
        uint2 u = make_uint2(packbf(v.x * sc + bi, v.y * sc + bi),
                             packbf(v.z * sc + bi, v.w * sc + bi));
        *reinterpret_cast<uint2*>(xnb + base + (size_t)i * 4) = u;
    }
}

// ============================================================================
// BF16 mma.sync GEMM, all-bf16 inputs.
// MODE 0: out bf16 (QKV); q rows (m < NC) scaled by 0.125 (= attn scale^2).
// MODE 1: out fp32 = C + bias + resid (proj).
// CTA 128x128, BK=32, 256 threads / 8 warps (warp tile 32x64),
// double-buffered smem, register-staged prefetch, uint pitch 20.
// ============================================================================
constexpr int GPU_ = 20;
constexpr int GSTG = 128 * GPU_;
constexpr int GEMM_SMEM = 2 * 2 * GSTG * 4;   // 40960 B

template <int MODE>
__global__ void __launch_bounds__(256) gemm_mma(
    const uint16_t* __restrict__ W, const uint16_t* __restrict__ X,
    const float* __restrict__ bias, const float* __restrict__ resid,
    uint16_t* __restrict__ Cb, float* __restrict__ Cf, int K,
    long strideB, long strideC, long strideR) {
    extern __shared__ uint32_t smu[];

    const int t = threadIdx.x;
    const int wid = t >> 5, lane = t & 31;
    const int gi = lane >> 2, li = lane & 3;
    const int wm0 = (wid & 3) * 32;
    const int wn0 = (wid >> 2) * 64;
    const int m0 = blockIdx.y * 128;
    const int n0 = blockIdx.x * 128;
    const int z  = blockIdx.z;

    const int arow = t >> 1;
    const int acu  = (t & 1) * 8;
    const uint16_t* Wp = W + (size_t)(m0 + arow) * K + (t & 1) * 16;
    const int bn   = t & 127;
    const int bku  = (t >> 7) * 8;
    const uint16_t* Xp = X + (size_t)z * strideB +
                         (size_t)((t >> 7) * 16) * NT + n0 + bn;

    float c[2][8][4];
#pragma unroll
    for (int mt = 0; mt < 2; mt++)
#pragma unroll
        for (int nt = 0; nt < 8; nt++)
#pragma unroll
            for (int i = 0; i < 4; i++) c[mt][nt][i] = 0.f;

    uint4 apre[2];
    uint32_t bpre[16];
    const int NIT = K / 32;

    apre[0] = *reinterpret_cast<const uint4*>(Wp);
    apre[1] = *reinterpret_cast<const uint4*>(Wp + 8);
#pragma unroll
    for (int j = 0; j < 16; j++) bpre[j] = Xp[(size_t)j * NT];
    {
        uint32_t* As = smu;
        uint32_t* Bs = smu + GSTG;
        *reinterpret_cast<uint4*>(&As[arow * GPU_ + acu])     = apre[0];
        *reinterpret_cast<uint4*>(&As[arow * GPU_ + acu + 4]) = apre[1];
        uint32_t ub[8];
#pragma unroll
        for (int j = 0; j < 8; j++) ub[j] = bpre[2 * j] | (bpre[2 * j + 1] << 16);
        *reinterpret_cast<uint4*>(&Bs[bn * GPU_ + bku])     = *reinterpret_cast<uint4*>(&ub[0]);
        *reinterpret_cast<uint4*>(&Bs[bn * GPU_ + bku + 4]) = *reinterpret_cast<uint4*>(&ub[4]);
    }
    __syncthreads();

    for (int it = 0; it < NIT; it++) {
        if (it + 1 < NIT) {
            const int k0 = (it + 1) * 32;
            apre[0] = *reinterpret_cast<const uint4*>(Wp + k0);
            apre[1] = *reinterpret_cast<const uint4*>(Wp + k0 + 8);
#pragma unroll
            for (int j = 0; j < 16; j++) bpre[j] = Xp[(size_t)(k0 + j) * NT];
        }

        const uint32_t* As = smu + (it & 1) * 2 * GSTG;
        const uint32_t* Bs = As + GSTG;
#pragma unroll
        for (int ks = 0; ks < 2; ks++) {
            const int ku = ks * 8;
            uint32_t a[2][4];
#pragma unroll
            for (int mt = 0; mt < 2; mt++) {
                int base = (wm0 + mt * 16 + gi) * GPU_ + ku + li;
                a[mt][0] = As[base];
                a[mt][1] = As[base + 8 * GPU_];
                a[mt][2] = As[base + 4];
                a[mt][3] = As[base + 8 * GPU_ + 4];
            }
            uint32_t b[8][2];
#pragma unroll
            for (int nt = 0; nt < 8; nt++) {
                int base = (wn0 + nt * 8 + gi) * GPU_ + ku + li;
                b[nt][0] = Bs[base];
                b[nt][1] = Bs[base + 4];
            }
#pragma unroll
            for (int mt = 0; mt < 2; mt++)
#pragma unroll
                for (int nt = 0; nt < 8; nt++)
                    mma_bf16(c[mt][nt], a[mt], b[nt]);
        }

        if (it + 1 < NIT) {
            uint32_t* Asn = smu + ((it + 1) & 1) * 2 * GSTG;
            uint32_t* Bsn = Asn + GSTG;
            *reinterpret_cast<uint4*>(&Asn[arow * GPU_ + acu])     = apre[0];
            *reinterpret_cast<uint4*>(&Asn[arow * GPU_ + acu + 4]) = apre[1];
            uint32_t ub[8];
#pragma unroll
            for (int j = 0; j < 8; j++) ub[j] = bpre[2 * j] | (bpre[2 * j + 1] << 16);
            *reinterpret_cast<uint4*>(&Bsn[bn * GPU_ + bku])     = *reinterpret_cast<uint4*>(&ub[0]);
            *reinterpret_cast<uint4*>(&Bsn[bn * GPU_ + bku + 4]) = *reinterpret_cast<uint4*>(&ub[4]);
            __syncthreads();
        }
    }

#pragma unroll
    for (int mt = 0; mt < 2; mt++) {
#pragma unroll
        for (int h = 0; h < 2; h++) {
            const int m = m0 + wm0 + mt * 16 + gi + h * 8;
            const float bv = bias[m];
            if (MODE == 0) {
                const float qs = (m < NC) ? 0.125f : 1.0f;  // scale^2 on q
                uint16_t* Cp = Cb + (size_t)z * strideC + (size_t)m * NT + n0 + wn0;
#pragma unroll
                for (int nt = 0; nt < 8; nt++) {
                    const int col = nt * 8 + 2 * li;
                    uint32_t p = packbf((c[mt][nt][2 * h + 0] + bv) * qs,
                                        (c[mt][nt][2 * h + 1] + bv) * qs);
                    *reinterpret_cast<uint32_t*>(Cp + col) = p;
                }
            } else {
                float* Cp = Cf + (size_t)z * strideC + (size_t)m * NT + n0 + wn0;
                const float* Rp = resid + (size_t)z * strideR + (size_t)m * NT + n0 + wn0;
#pragma unroll
                for (int nt = 0; nt < 8; nt++) {
                    const int col = nt * 8 + 2 * li;
                    float2 rv = *reinterpret_cast<const float2*>(Rp + col);
                    float2 o;
                    o.x = c[mt][nt][2 * h + 0] + bv + rv.x;
                    o.y = c[mt][nt][2 * h + 1] + bv + rv.y;
                    *reinterpret_cast<float2*>(Cp + col) = o;
                }
            }
        }
    }
}

// ============================================================================
// Flash attention, bf16 in/out, register softmax.
// Block = (64-query tile, head). 256 threads / 8 warps; warp tile 16x32.
// Scale baked into q (0.125 at QKV epilogue) — no scaling here.
// Smem (uints, pitch 36): Qu[i][c], Ku[j][c], Vu[c][j], Pu[i][j]; plus
// fp32 mrow/lrow/arow[64], redm[128], redl[128].
// 4 barriers per kv-step.
// ============================================================================
constexpr int APU = 36;
constexpr int ATU = 64 * APU;                       // 2304 uints
constexpr int ATT_SMEM = (4 * ATU + 3 * 64 + 256) * 4;   // 38656 B

__global__ void __launch_bounds__(256) attn_mma(
    const uint16_t* __restrict__ qkv, uint16_t* __restrict__ attn_out) {
    extern __shared__ uint32_t smu[];
    uint32_t* Qu = smu;
    uint32_t* Ku = Qu + ATU;
    uint32_t* Vu = Ku + ATU;
    uint32_t* Pu = Vu + ATU;
    float* mrow = reinterpret_cast<float*>(smu + 4 * ATU);
    float* lrow = mrow + 64;
    float* arow = lrow + 64;
    float* redm = arow + 64;   // [2][64]
    float* redl = redm + 128;  // [2][64]

    const int tid  = threadIdx.x;
    const int wid  = tid >> 5, lane = tid & 31;
    const int gi   = lane >> 2, li = lane & 3;
    const int wm16 = (wid & 3) * 16;   // S: i base; O: c base
    const int wn32 = (wid >> 2) * 32;  // S: j base; O: i base
    const int half = wid >> 2;
    const int qt0  = blockIdx.x * 64;
    const int b    = blockIdx.y >> 4, h = blockIdx.y & 15;
    const size_t qbase = ((size_t)b * 3 * NC + (size_t)h * CH) * NT;
    const size_t kbase = qbase + (size_t)NC * NT;
    const size_t vbase = qbase + 2 * (size_t)NC * NT;

    // Q transposed: Qu[i][c-pairs]
#pragma unroll
    for (int l = 0; l < 4; l++) {
        int idx = tid + 256 * l;
        int ii  = idx & 63;
        int c4  = (idx >> 6) * 4;
        const uint16_t* p = qkv + qbase + (size_t)c4 * NT + qt0 + ii;
        uint32_t q0 = p[0], q1 = p[NT], q2 = p[2 * NT], q3 = p[3 * NT];
        uint2 u = make_uint2(q0 | (q1 << 16), q2 | (q3 << 16));
        *reinterpret_cast<uint2*>(&Qu[ii * APU + (c4 >> 1)]) = u;
    }
    if (tid < 64) { mrow[tid] = -1e30f; lrow[tid] = 0.f; }

    float oacc[4][4];
#pragma unroll
    for (int nt = 0; nt < 4; nt++)
#pragma unroll
        for (int i = 0; i < 4; i++) oacc[nt][i] = 0.f;

    const int r0 = wm16 + gi, r1 = r0 + 8;

    for (int s0 = 0; s0 < NT; s0 += 64) {
        __syncthreads();   // guard K/V/Pu overwrite vs previous O-mma
        // K transposed: Ku[j][c-pairs]
#pragma unroll
        for (int l = 0; l < 4; l++) {
            int idx = tid + 256 * l;
            int jj  = idx & 63;
            int c4  = (idx >> 6) * 4;
            const uint16_t* p = qkv + kbase + (size_t)c4 * NT + s0 + jj;
            uint32_t k0 = p[0], k1 = p[NT], k2 = p[2 * NT], k3 = p[3 * NT];
            uint2 u = make_uint2(k0 | (k1 << 16), k2 | (k3 << 16));
            *reinterpret_cast<uint2*>(&Ku[jj * APU + (c4 >> 1)]) = u;
        }
        // V direct: Vu[c][j-pairs]
#pragma unroll
        for (int l = 0; l < 4; l++) {
            int idx = tid + 256 * l;
            int c   = idx >> 4;
            int j4  = (idx & 15) * 4;
            uint2 v = *reinterpret_cast<const uint2*>(
                qkv + vbase + (size_t)c * NT + s0 + j4);
            *reinterpret_cast<uint2*>(&Vu[c * APU + (j4 >> 1)]) = v;
        }
        __syncthreads();

        // ---- S = Q^T K ----
        float sacc[4][4];
#pragma unroll
        for (int nt = 0; nt < 4; nt++)
#pragma unroll
            for (int i = 0; i < 4; i++) sacc[nt][i] = 0.f;
#pragma unroll
        for (int ks = 0; ks < 4; ks++) {
            const int ku = ks * 8;
            uint32_t a[4];
            const int ra = r0 * APU + ku + li;
            a[0] = Qu[ra];
            a[1] = Qu[ra + 8 * APU];
            a[2] = Qu[ra + 4];
            a[3] = Qu[ra + 8 * APU + 4];
#pragma unroll
            for (int nt = 0; nt < 4; nt++) {
                const int rb = (wn32 + nt * 8 + gi) * APU + ku + li;
                uint32_t bf[2] = {Ku[rb], Ku[rb + 4]};
                mma_bf16(sacc[nt], a, bf);
            }
        }

        // ---- phase A: per-warp row maxima (register + shuffle) ----
        float mx0 = -1e30f, mx1 = -1e30f;
#pragma unroll
        for (int nt = 0; nt < 4; nt++) {
            mx0 = fmaxf(mx0, fmaxf(sacc[nt][0], sacc[nt][1]));
            mx1 = fmaxf(mx1, fmaxf(sacc[nt][2], sacc[nt][3]));
        }
        mx0 = fmaxf(mx0, __shfl_xor_sync(0xffffffffu, mx0, 1));
        mx0 = fmaxf(mx0, __shfl_xor_sync(0xffffffffu, mx0, 2));
        mx1 = fmaxf(mx1, __shfl_xor_sync(0xffffffffu, mx1, 1));
        mx1 = fmaxf(mx1, __shfl_xor_sync(0xffffffffu, mx1, 2));
        const float mold0 = mrow[r0], mold1 = mrow[r1];
        if (li == 0) {
            redm[half * 64 + r0] = mx0;
            redm[half * 64 + r1] = mx1;
        }
        __syncthreads();

        // ---- phase B: exp in regs, bf16 probs to Pu, partial sums ----
        const float m0 = fmaxf(mold0, fmaxf(redm[r0], redm[64 + r0]));
        const float m1 = fmaxf(mold1, fmaxf(redm[r1], redm[64 + r1]));
        float s0s = 0.f, s1s = 0.f;
#pragma unroll
        for (int nt = 0; nt < 4; nt++) {
            uint32_t p01 = packbf(__expf(sacc[nt][0] - m0),
                                  __expf(sacc[nt][1] - m0));
            s0s += __uint_as_float(p01 << 16) +
                   __uint_as_float(p01 & 0xFFFF0000u);
            Pu[r0 * APU + (wn32 >> 1) + 4 * nt + li] = p01;
            uint32_t p23 = packbf(__expf(sacc[nt][2] - m1),
                                  __expf(sacc[nt][3] - m1));
            s1s += __uint_as_float(p23 << 16) +
                   __uint_as_float(p23 & 0xFFFF0000u);
            Pu[r1 * APU + (wn32 >> 1) + 4 * nt + li] = p23;
        }
        s0s += __shfl_xor_sync(0xffffffffu, s0s, 1);
        s0s += __shfl_xor_sync(0xffffffffu, s0s, 2);
        s1s += __shfl_xor_sync(0xffffffffu, s1s, 1);
        s1s += __shfl_xor_sync(0xffffffffu, s1s, 2);
        if (li == 0) {
            redl[half * 64 + r0] = s0s;
            redl[half * 64 + r1] = s1s;
            if (half == 0) {
                arow[r0] = __expf(mold0 - m0); mrow[r0] = m0;
                arow[r1] = __expf(mold1 - m1); mrow[r1] = m1;
            }
        }
        __syncthreads();

        // ---- phase C: l update (designated), rescale O, O = V P^T ----
        if (li == 0 && half == 0) {
            lrow[r0] = lrow[r0] * arow[r0] + redl[r0] + redl[64 + r0];
            lrow[r1] = lrow[r1] * arow[r1] + redl[r1] + redl[64 + r1];
        }
#pragma unroll
        for (int nt = 0; nt < 4; nt++) {
            const float a0 = arow[wn32 + nt * 8 + 2 * li];
            const float a1 = arow[wn32 + nt * 8 + 2 * li + 1];
            oacc[nt][0] *= a0; oacc[nt][1] *= a1;
            oacc[nt][2] *= a0; oacc[nt][3] *= a1;
        }
#pragma unroll
        for (int ks = 0; ks < 4; ks++) {
            const int ku = ks * 8;
            uint32_t a[4];
            const int ra = r0 * APU + ku + li;
            a[0] = Vu[ra];
            a[1] = Vu[ra + 8 * APU];
            a[2] = Vu[ra + 4];
            a[3] = Vu[ra + 8 * APU + 4];
#pragma unroll
            for (int nt = 0; nt < 4; nt++) {
                const int rb = (wn32 + nt * 8 + gi) * APU + ku + li;
                uint32_t bf[2] = {Pu[rb], Pu[rb + 4]};
                mma_bf16(oacc[nt], a, bf);
            }
        }
    }
    __syncthreads();

    // Epilogue: O[c][i] /= l[i], bf16 out
    const size_t abase = ((size_t)b * NC + (size_t)h * CH) * NT;
#pragma unroll
    for (int nt = 0; nt < 4; nt++) {
        const int i = wn32 + nt * 8 + 2 * li;
        const float l0 = 1.f / lrow[i];
        const float l1 = 1.f / lrow[i + 1];
        *reinterpret_cast<uint32_t*>(
            &attn_out[abase + (size_t)r0 * NT + qt0 + i]) =
            packbf(oacc[nt][0] * l0, oacc[nt][1] * l1);
        *reinterpret_cast<uint32_t*>(
            &attn_out[abase + (size_t)r1 * NT + qt0 + i]) =
            packbf(oacc[nt][2] * l0, oacc[nt][3] * l1);
    }
}

// ---------------------------------------------------------------------------
extern "C" void kernel_launch(void* const* d_in, const int* in_sizes, int n_in,
                              void* d_out, int out_size) {
    const float* x        = (const float*)d_in[0];
    const float* gn_scale = (const float*)d_in[1];
    const float* gn_bias  = (const float*)d_in[2];
    const float* qkv_w    = (const float*)d_in[3];
    const float* qkv_b    = (const float*)d_in[4];
    const float* proj_w   = (const float*)d_in[5];
    const float* proj_b   = (const float*)d_in[6];
    float* out = (float*)d_out;

    uint16_t *xnb, *qkvb, *attnb, *wqb, *wpb;
    cudaGetSymbolAddress((void**)&xnb,  g_xnb);
    cudaGetSymbolAddress((void**)&qkvb, g_qkvb);
    cudaGetSymbolAddress((void**)&attnb, g_attnb);
    cudaGetSymbolAddress((void**)&wqb,  g_wqb);
    cudaGetSymbolAddress((void**)&wpb,  g_wpb);

    // 0) Weights -> bf16
    wconv<<<(3 * NC * NC / 4 + 255) / 256, 256>>>(qkv_w, wqb, 3 * NC * NC);
    wconv<<<(NC * NC / 4 + 255) / 256, 256>>>(proj_w, wpb, NC * NC);

    // 1) GroupNorm -> bf16
    gn_kernel<<<NB * NG, 512>>>(x, gn_scale, gn_bias, xnb);

    // 2) QKV GEMM (bf16 in/out, q pre-scaled by 0.125)
    cudaFuncSetAttribute(gemm_mma<0>,
                         cudaFuncAttributeMaxDynamicSharedMemorySize, GEMM_SMEM);
    cudaFuncSetAttribute(gemm_mma<1>,
                         cudaFuncAttributeMaxDynamicSharedMemorySize, GEMM_SMEM);
    dim3 gq(NT / 128, 3 * NC / 128, NB);
    gemm_mma<0><<<gq, 256, GEMM_SMEM>>>(wqb, xnb, qkv_b, nullptr, qkvb, nullptr,
                                        NC, (long)NC * NT, (long)3 * NC * NT, 0L);

    // 3) Flash attention (bf16, register softmax)
    cudaFuncSetAttribute(attn_mma,
                         cudaFuncAttributeMaxDynamicSharedMemorySize, ATT_SMEM);
    attn_mma<<<dim3(NT / 64, NB * NH), 256, ATT_SMEM>>>(qkvb, attnb);

    // 4) Proj GEMM (bf16 in, fp32 out + bias + residual)
    dim3 gp(NT / 128, NC / 128, NB);
    gemm_mma<1><<<gp, 256, GEMM_SMEM>>>(wpb, attnb, proj_b, x, nullptr, out,
                                        NC, (long)NC * NT, (long)NC * NT,
                                        (long)NC * NT);
}

// round 7
// speedup vs baseline: 5.0591x; 1.1363x over previous
#include <cuda_runtime.h>
#include <cstdint>

constexpr int NB = 4;      // batch
constexpr int NC = 1024;   // channels
constexpr int NT = 2048;   // time
constexpr int NH = 16;     // heads
constexpr int NG = 32;     // groups
constexpr int CPG = NC / NG;   // 32 channels per group
constexpr int CH  = NC / NH;   // 64 channels per head
constexpr float EPS = 1e-5f;

// Scratch (device globals) — bf16 stored as uint16_t
__device__ uint16_t g_xnb [NB * NC * NT];
__device__ uint16_t g_qkvb[NB * 3 * NC * NT];
__device__ uint16_t g_attnb[NB * NC * NT];
__device__ uint16_t g_wqb [3 * NC * NC];
__device__ uint16_t g_wpb [NC * NC];

__device__ __forceinline__ uint32_t packbf(float lo, float hi) {
    uint32_t r;
    asm("cvt.rn.bf16x2.f32 %0, %1, %2;" : "=r"(r) : "f"(hi), "f"(lo));
    return r;
}

__device__ __forceinline__ void mma_bf16(float* c, const uint32_t* a,
                                         const uint32_t* b) {
    asm volatile(
        "mma.sync.aligned.m16n8k16.row.col.f32.bf16.bf16.f32 "
        "{%0,%1,%2,%3}, {%4,%5,%6,%7}, {%8,%9}, {%0,%1,%2,%3};"
        : "+f"(c[0]), "+f"(c[1]), "+f"(c[2]), "+f"(c[3])
        : "r"(a[0]), "r"(a[1]), "r"(a[2]), "r"(a[3]), "r"(b[0]), "r"(b[1]));
}

__device__ __forceinline__ uint32_t smem_u32(const void* p) {
    uint32_t a;
    asm("{ .reg .u64 t; cvta.to.shared.u64 t, %1; cvt.u32.u64 %0, t; }"
        : "=r"(a) : "l"(p));
    return a;
}

__device__ __forceinline__ void ldsm4(uint32_t* r, uint32_t addr) {
    asm volatile(
        "ldmatrix.sync.aligned.m8n8.x4.shared.b16 {%0,%1,%2,%3}, [%4];"
        : "=r"(r[0]), "=r"(r[1]), "=r"(r[2]), "=r"(r[3]) : "r"(addr));
}

// ============================================================================
// Weight conversion fp32 -> bf16
// ============================================================================
__global__ void wconv(const float* __restrict__ W, uint16_t* __restrict__ Wb,
                      int n) {
    int i = (blockIdx.x * blockDim.x + threadIdx.x) * 4;
    if (i < n) {
        float4 v = *reinterpret_cast<const float4*>(W + i);
        uint2 u = make_uint2(packbf(v.x, v.y), packbf(v.z, v.w));
        *reinterpret_cast<uint2*>(Wb + i) = u;
    }
}

// ============================================================================
// GroupNorm(32, C) -> bf16 output (validated)
// ============================================================================
__global__ void gn_kernel(const float* __restrict__ x,
                          const float* __restrict__ gamma,
                          const float* __restrict__ beta,
                          uint16_t* __restrict__ xnb) {
    const int b = blockIdx.x / NG;
    const int g = blockIdx.x % NG;
    const int n = CPG * NT;
    const size_t base = ((size_t)b * NC + (size_t)g * CPG) * NT;
    const float4* xv = reinterpret_cast<const float4*>(x + base);
    const int nv = n / 4;

    float s = 0.f, sq = 0.f;
    for (int i = threadIdx.x; i < nv; i += blockDim.x) {
        float4 v = xv[i];
        s  += v.x + v.y + v.z + v.w;
        sq += v.x * v.x + v.y * v.y + v.z * v.z + v.w * v.w;
    }
    __shared__ float ss[512], sq2[512];
    ss[threadIdx.x] = s; sq2[threadIdx.x] = sq;
    __syncthreads();
    for (int o = blockDim.x >> 1; o > 0; o >>= 1) {
        if (threadIdx.x < (unsigned)o) {
            ss[threadIdx.x]  += ss[threadIdx.x + o];
            sq2[threadIdx.x] += sq2[threadIdx.x + o];
        }
        __syncthreads();
    }
    __shared__ float smean, srstd;
    if (threadIdx.x == 0) {
        float m   = ss[0] / n;
        float var = sq2[0] / n - m * m;
        smean = m;
        srstd = rsqrtf(var + EPS);
    }
    __syncthreads();
    const float m = smean, r = srstd;
    for (int i = threadIdx.x; i < nv; i += blockDim.x) {
        int c = g * CPG + (i >> 9);
        float sc = gamma[c] * r;
        float bi = beta[c] - m * sc;
        float4 v = xv[i];
        uint2 u = make_uint2(packbf(v.x * sc + bi, v.y * sc + bi),
                             packbf(v.z * sc + bi, v.w * sc + bi));
        *reinterpret_cast<uint2*>(xnb + base + (size_t)i * 4) = u;
    }
}

// ============================================================================
// BF16 mma.sync GEMM with ldmatrix fragment loads.
// MODE 0: out bf16 (QKV); q rows (m < NC) scaled by 0.125.
// MODE 1: out fp32 = C + bias + resid (proj).
// CTA 128x128, BK=32, 256 threads / 8 warps (warp tile 32x64),
// double-buffered smem (uint pitch 20), register-staged prefetch.
// ============================================================================
constexpr int GPU_ = 20;
constexpr int GSTG = 128 * GPU_;
constexpr int GEMM_SMEM = 2 * 2 * GSTG * 4;   // 40960 B

template <int MODE>
__global__ void __launch_bounds__(256) gemm_mma(
    const uint16_t* __restrict__ W, const uint16_t* __restrict__ X,
    const float* __restrict__ bias, const float* __restrict__ resid,
    uint16_t* __restrict__ Cb, float* __restrict__ Cf, int K,
    long strideB, long strideC, long strideR) {
    extern __shared__ uint32_t smu[];

    const int t = threadIdx.x;
    const int wid = t >> 5, lane = t & 31;
    const int gi = lane >> 2, li = lane & 3;
    const int wm0 = (wid & 3) * 32;
    const int wn0 = (wid >> 2) * 64;
    const int m0 = blockIdx.y * 128;
    const int n0 = blockIdx.x * 128;
    const int z  = blockIdx.z;

    // ldmatrix lane patterns
    const int laneRowA = lane & 15;
    const int laneKA   = (lane >> 4) << 2;
    const int laneRowB = (lane & 7) | ((lane >> 4) << 3);
    const int laneKB   = ((lane >> 3) & 1) << 2;
    const int aIdx = (wm0 + laneRowA) * GPU_ + laneKA;   // + mt*16*GPU_ + ku
    const int bIdx = (wn0 + laneRowB) * GPU_ + laneKB;   // + g*16*GPU_ + ku
    const uint32_t smb = smem_u32(smu);

    const int arow = t >> 1;
    const int acu  = (t & 1) * 8;
    const uint16_t* Wp = W + (size_t)(m0 + arow) * K + (t & 1) * 16;
    const int bn   = t & 127;
    const int bku  = (t >> 7) * 8;
    const uint16_t* Xp = X + (size_t)z * strideB +
                         (size_t)((t >> 7) * 16) * NT + n0 + bn;

    float c[2][8][4];
#pragma unroll
    for (int mt = 0; mt < 2; mt++)
#pragma unroll
        for (int nt = 0; nt < 8; nt++)
#pragma unroll
            for (int i = 0; i < 4; i++) c[mt][nt][i] = 0.f;

    uint4 apre[2];
    uint32_t bpre[16];
    const int NIT = K / 32;

    apre[0] = *reinterpret_cast<const uint4*>(Wp);
    apre[1] = *reinterpret_cast<const uint4*>(Wp + 8);
#pragma unroll
    for (int j = 0; j < 16; j++) bpre[j] = Xp[(size_t)j * NT];
    {
        uint32_t* As = smu;
        uint32_t* Bs = smu + GSTG;
        *reinterpret_cast<uint4*>(&As[arow * GPU_ + acu])     = apre[0];
        *reinterpret_cast<uint4*>(&As[arow * GPU_ + acu + 4]) = apre[1];
        uint32_t ub[8];
#pragma unroll
        for (int j = 0; j < 8; j++) ub[j] = bpre[2 * j] | (bpre[2 * j + 1] << 16);
        *reinterpret_cast<uint4*>(&Bs[bn * GPU_ + bku])     = *reinterpret_cast<uint4*>(&ub[0]);
        *reinterpret_cast<uint4*>(&Bs[bn * GPU_ + bku + 4]) = *reinterpret_cast<uint4*>(&ub[4]);
    }
    __syncthreads();

    for (int it = 0; it < NIT; it++) {
        if (it + 1 < NIT) {
            const int k0 = (it + 1) * 32;
            apre[0] = *reinterpret_cast<const uint4*>(Wp + k0);
            apre[1] = *reinterpret_cast<const uint4*>(Wp + k0 + 8);
#pragma unroll
            for (int j = 0; j < 16; j++) bpre[j] = Xp[(size_t)(k0 + j) * NT];
        }

        const uint32_t asb = smb + ((it & 1) * 2 * GSTG) * 4;
        const uint32_t bsb = asb + GSTG * 4;
#pragma unroll
        for (int ks = 0; ks < 2; ks++) {
            const int ku = ks * 8;
            uint32_t a[2][4];
            ldsm4(a[0], asb + 4 * (aIdx + ku));
            ldsm4(a[1], asb + 4 * (aIdx + 16 * GPU_ + ku));
            uint32_t bb[4][4];
#pragma unroll
            for (int g = 0; g < 4; g++)
                ldsm4(bb[g], bsb + 4 * (bIdx + g * 16 * GPU_ + ku));
#pragma unroll
            for (int mt = 0; mt < 2; mt++)
#pragma unroll
                for (int g = 0; g < 4; g++) {
                    mma_bf16(c[mt][2 * g],     a[mt], &bb[g][0]);
                    mma_bf16(c[mt][2 * g + 1], a[mt], &bb[g][2]);
                }
        }

        if (it + 1 < NIT) {
            uint32_t* Asn = smu + ((it + 1) & 1) * 2 * GSTG;
            uint32_t* Bsn = Asn + GSTG;
            *reinterpret_cast<uint4*>(&Asn[arow * GPU_ + acu])     = apre[0];
            *reinterpret_cast<uint4*>(&Asn[arow * GPU_ + acu + 4]) = apre[1];
            uint32_t ub[8];
#pragma unroll
            for (int j = 0; j < 8; j++) ub[j] = bpre[2 * j] | (bpre[2 * j + 1] << 16);
            *reinterpret_cast<uint4*>(&Bsn[bn * GPU_ + bku])     = *reinterpret_cast<uint4*>(&ub[0]);
            *reinterpret_cast<uint4*>(&Bsn[bn * GPU_ + bku + 4]) = *reinterpret_cast<uint4*>(&ub[4]);
            __syncthreads();
        }
    }

#pragma unroll
    for (int mt = 0; mt < 2; mt++) {
#pragma unroll
        for (int h = 0; h < 2; h++) {
            const int m = m0 + wm0 + mt * 16 + gi + h * 8;
            const float bv = bias[m];
            if (MODE == 0) {
                const float qs = (m < NC) ? 0.125f : 1.0f;
                uint16_t* Cp = Cb + (size_t)z * strideC + (size_t)m * NT + n0 + wn0;
#pragma unroll
                for (int nt = 0; nt < 8; nt++) {
                    const int col = nt * 8 + 2 * li;
                    uint32_t p = packbf((c[mt][nt][2 * h + 0] + bv) * qs,
                                        (c[mt][nt][2 * h + 1] + bv) * qs);
                    *reinterpret_cast<uint32_t*>(Cp + col) = p;
                }
            } else {
                float* Cp = Cf + (size_t)z * strideC + (size_t)m * NT + n0 + wn0;
                const float* Rp = resid + (size_t)z * strideR + (size_t)m * NT + n0 + wn0;
#pragma unroll
                for (int nt = 0; nt < 8; nt++) {
                    const int col = nt * 8 + 2 * li;
                    float2 rv = *reinterpret_cast<const float2*>(Rp + col);
                    float2 o;
                    o.x = c[mt][nt][2 * h + 0] + bv + rv.x;
                    o.y = c[mt][nt][2 * h + 1] + bv + rv.y;
                    *reinterpret_cast<float2*>(Cp + col) = o;
                }
            }
        }
    }
}

// ============================================================================
// Flash attention, bf16, register softmax, ldmatrix fragments,
// register-prefetched K/V (gmem loads overlap softmax phases).
// Block = (64-query tile, head). 256 threads / 8 warps; warp tile 16x32.
// ============================================================================
constexpr int APU = 36;
constexpr int ATU = 64 * APU;
constexpr int ATT_SMEM = (4 * ATU + 3 * 64 + 256) * 4;   // 38656 B

__global__ void __launch_bounds__(256) attn_mma(
    const uint16_t* __restrict__ qkv, uint16_t* __restrict__ attn_out) {
    extern __shared__ uint32_t smu[];
    uint32_t* Qu = smu;
    uint32_t* Ku = Qu + ATU;
    uint32_t* Vu = Ku + ATU;
    uint32_t* Pu = Vu + ATU;
    float* mrow = reinterpret_cast<float*>(smu + 4 * ATU);
    float* lrow = mrow + 64;
    float* arow = lrow + 64;
    float* redm = arow + 64;   // [2][64]
    float* redl = redm + 128;  // [2][64]

    const int tid  = threadIdx.x;
    const int wid  = tid >> 5, lane = tid & 31;
    const int gi   = lane >> 2, li = lane & 3;
    const int wm16 = (wid & 3) * 16;
    const int wn32 = (wid >> 2) * 32;
    const int half = wid >> 2;
    const int qt0  = blockIdx.x * 64;
    const int b    = blockIdx.y >> 4, h = blockIdx.y & 15;
    const size_t qbase = ((size_t)b * 3 * NC + (size_t)h * CH) * NT;
    const size_t kbase = qbase + (size_t)NC * NT;
    const size_t vbase = qbase + 2 * (size_t)NC * NT;

    // ldmatrix lane patterns
    const int laneRowA = lane & 15;
    const int laneKA   = (lane >> 4) << 2;
    const int laneRowB = (lane & 7) | ((lane >> 4) << 3);
    const int laneKB   = ((lane >> 3) & 1) << 2;
    const int aIdx = (wm16 + laneRowA) * APU + laneKA;   // rows for Qu / Vu
    const int bIdx = (wn32 + laneRowB) * APU + laneKB;   // rows for Ku / Pu
    const uint32_t qb_ = smem_u32(Qu), kb_ = smem_u32(Ku);
    const uint32_t vb_ = smem_u32(Vu), pb_ = smem_u32(Pu);

    // Q transposed: Qu[i][c-pairs]
#pragma unroll
    for (int l = 0; l < 4; l++) {
        int idx = tid + 256 * l;
        int ii  = idx & 63;
        int c4  = (idx >> 6) * 4;
        const uint16_t* p = qkv + qbase + (size_t)c4 * NT + qt0 + ii;
        uint32_t q0 = p[0], q1 = p[NT], q2 = p[2 * NT], q3 = p[3 * NT];
        uint2 u = make_uint2(q0 | (q1 << 16), q2 | (q3 << 16));
        *reinterpret_cast<uint2*>(&Qu[ii * APU + (c4 >> 1)]) = u;
    }
    if (tid < 64) { mrow[tid] = -1e30f; lrow[tid] = 0.f; }

    float oacc[4][4];
#pragma unroll
    for (int nt = 0; nt < 4; nt++)
#pragma unroll
        for (int i = 0; i < 4; i++) oacc[nt][i] = 0.f;

    const int r0 = wm16 + gi, r1 = r0 + 8;

    // prefetch kv-step 0 into registers
    uint2 kpre[4], vpre[4];
#pragma unroll
    for (int l = 0; l < 4; l++) {
        int idx = tid + 256 * l;
        int jj  = idx & 63;
        int c4  = (idx >> 6) * 4;
        const uint16_t* p = qkv + kbase + (size_t)c4 * NT + jj;
        kpre[l] = make_uint2(p[0] | ((uint32_t)p[NT] << 16),
                             p[2 * NT] | ((uint32_t)p[3 * NT] << 16));
        int c  = idx >> 4;
        int j4 = (idx & 15) * 4;
        vpre[l] = *reinterpret_cast<const uint2*>(qkv + vbase + (size_t)c * NT + j4);
    }

    for (int s0 = 0; s0 < NT; s0 += 64) {
        __syncthreads();   // prior O-mma done reading Ku/Vu/Pu
        // store prefetched K/V
#pragma unroll
        for (int l = 0; l < 4; l++) {
            int idx = tid + 256 * l;
            int jj  = idx & 63;
            int c4  = (idx >> 6) * 4;
            *reinterpret_cast<uint2*>(&Ku[jj * APU + (c4 >> 1)]) = kpre[l];
            int c  = idx >> 4;
            int j4 = (idx & 15) * 4;
            *reinterpret_cast<uint2*>(&Vu[c * APU + (j4 >> 1)]) = vpre[l];
        }
        __syncthreads();

        // ---- S = Q^T K ----
        float sacc[4][4];
#pragma unroll
        for (int nt = 0; nt < 4; nt++)
#pragma unroll
            for (int i = 0; i < 4; i++) sacc[nt][i] = 0.f;
#pragma unroll
        for (int ks = 0; ks < 4; ks++) {
            const int ku = ks * 8;
            uint32_t a[4];
            ldsm4(a, qb_ + 4 * (aIdx + ku));
            uint32_t bb[2][4];
            ldsm4(bb[0], kb_ + 4 * (bIdx + ku));
            ldsm4(bb[1], kb_ + 4 * (bIdx + 16 * APU + ku));
            mma_bf16(sacc[0], a, &bb[0][0]);
            mma_bf16(sacc[1], a, &bb[0][2]);
            mma_bf16(sacc[2], a, &bb[1][0]);
            mma_bf16(sacc[3], a, &bb[1][2]);
        }

        // prefetch next kv-step (latency hidden behind softmax)
        if (s0 + 64 < NT) {
#pragma unroll
            for (int l = 0; l < 4; l++) {
                int idx = tid + 256 * l;
                int jj  = idx & 63;
                int c4  = (idx >> 6) * 4;
                const uint16_t* p = qkv + kbase + (size_t)c4 * NT + s0 + 64 + jj;
                kpre[l] = make_uint2(p[0] | ((uint32_t)p[NT] << 16),
                                     p[2 * NT] | ((uint32_t)p[3 * NT] << 16));
                int c  = idx >> 4;
                int j4 = (idx & 15) * 4;
                vpre[l] = *reinterpret_cast<const uint2*>(
                    qkv + vbase + (size_t)c * NT + s0 + 64 + j4);
            }
        }

        // ---- phase A: per-warp row maxima ----
        float mx0 = -1e30f, mx1 = -1e30f;
#pragma unroll
        for (int nt = 0; nt < 4; nt++) {
            mx0 = fmaxf(mx0, fmaxf(sacc[nt][0], sacc[nt][1]));
            mx1 = fmaxf(mx1, fmaxf(sacc[nt][2], sacc[nt][3]));
        }
        mx0 = fmaxf(mx0, __shfl_xor_sync(0xffffffffu, mx0, 1));
        mx0 = fmaxf(mx0, __shfl_xor_sync(0xffffffffu, mx0, 2));
        mx1 = fmaxf(mx1, __shfl_xor_sync(0xffffffffu, mx1, 1));
        mx1 = fmaxf(mx1, __shfl_xor_sync(0xffffffffu, mx1, 2));
        const float mold0 = mrow[r0], mold1 = mrow[r1];
        if (li == 0) {
            redm[half * 64 + r0] = mx0;
            redm[half * 64 + r1] = mx1;
        }
        __syncthreads();

        // ---- phase B: exp, bf16 probs to Pu, partial sums ----
        const float m0 = fmaxf(mold0, fmaxf(redm[r0], redm[64 + r0]));
        const float m1 = fmaxf(mold1, fmaxf(redm[r1], redm[64 + r1]));
        float s0s = 0.f, s1s = 0.f;
#pragma unroll
        for (int nt = 0; nt < 4; nt++) {
            uint32_t p01 = packbf(__expf(sacc[nt][0] - m0),
                                  __expf(sacc[nt][1] - m0));
            s0s += __uint_as_float(p01 << 16) +
                   __uint_as_float(p01 & 0xFFFF0000u);
            Pu[r0 * APU + (wn32 >> 1) + 4 * nt + li] = p01;
            uint32_t p23 = packbf(__expf(sacc[nt][2] - m1),
                                  __expf(sacc[nt][3] - m1));
            s1s += __uint_as_float(p23 << 16) +
                   __uint_as_float(p23 & 0xFFFF0000u);
            Pu[r1 * APU + (wn32 >> 1) + 4 * nt + li] = p23;
        }
        s0s += __shfl_xor_sync(0xffffffffu, s0s, 1);
        s0s += __shfl_xor_sync(0xffffffffu, s0s, 2);
        s1s += __shfl_xor_sync(0xffffffffu, s1s, 1);
        s1s += __shfl_xor_sync(0xffffffffu, s1s, 2);
        if (li == 0) {
            redl[half * 64 + r0] = s0s;
            redl[half * 64 + r1] = s1s;
            if (half == 0) {
                arow[r0] = __expf(mold0 - m0); mrow[r0] = m0;
                arow[r1] = __expf(mold1 - m1); mrow[r1] = m1;
            }
        }
        __syncthreads();

        // ---- phase C: l update, rescale O, O = V P^T ----
        if (li == 0 && half == 0) {
            lrow[r0] = lrow[r0] * arow[r0] + redl[r0] + redl[64 + r0];
            lrow[r1] = lrow[r1] * arow[r1] + redl[r1] + redl[64 + r1];
        }
#pragma unroll
        for (int nt = 0; nt < 4; nt++) {
            const float a0 = arow[wn32 + nt * 8 + 2 * li];
            const float a1 = arow[wn32 + nt * 8 + 2 * li + 1];
            oacc[nt][0] *= a0; oacc[nt][1] *= a1;
            oacc[nt][2] *= a0; oacc[nt][3] *= a1;
        }
#pragma unroll
        for (int ks = 0; ks < 4; ks++) {
            const int ku = ks * 8;
            uint32_t a[4];
            ldsm4(a, vb_ + 4 * (aIdx + ku));
            uint32_t bb[2][4];
            ldsm4(bb[0], pb_ + 4 * (bIdx + ku));
            ldsm4(bb[1], pb_ + 4 * (bIdx + 16 * APU + ku));
            mma_bf16(oacc[0], a, &bb[0][0]);
            mma_bf16(oacc[1], a, &bb[0][2]);
            mma_bf16(oacc[2], a, &bb[1][0]);
            mma_bf16(oacc[3], a, &bb[1][2]);
        }
    }
    __syncthreads();

    // Epilogue: O[c][i] /= l[i], bf16 out
    const size_t abase = ((size_t)b * NC + (size_t)h * CH) * NT;
#pragma unroll
    for (int nt = 0; nt < 4; nt++) {
        const int i = wn32 + nt * 8 + 2 * li;
        const float l0 = 1.f / lrow[i];
        const float l1 = 1.f / lrow[i + 1];
        *reinterpret_cast<uint32_t*>(
            &attn_out[abase + (size_t)r0 * NT + qt0 + i]) =
            packbf(oacc[nt][0] * l0, oacc[nt][1] * l1);
        *reinterpret_cast<uint32_t*>(
            &attn_out[abase + (size_t)r1 * NT + qt0 + i]) =
            packbf(oacc[nt][2] * l0, oacc[nt][3] * l1);
    }
}

// ---------------------------------------------------------------------------
extern "C" void kernel_launch(void* const* d_in, const int* in_sizes, int n_in,
                              void* d_out, int out_size) {
    const float* x        = (const float*)d_in[0];
    const float* gn_scale = (const float*)d_in[1];
    const float* gn_bias  = (const float*)d_in[2];
    const float* qkv_w    = (const float*)d_in[3];
    const float* qkv_b    = (const float*)d_in[4];
    const float* proj_w   = (const float*)d_in[5];
    const float* proj_b   = (const float*)d_in[6];
    float* out = (float*)d_out;

    uint16_t *xnb, *qkvb, *attnb, *wqb, *wpb;
    cudaGetSymbolAddress((void**)&xnb,  g_xnb);
    cudaGetSymbolAddress((void**)&qkvb, g_qkvb);
    cudaGetSymbolAddress((void**)&attnb, g_attnb);
    cudaGetSymbolAddress((void**)&wqb,  g_wqb);
    cudaGetSymbolAddress((void**)&wpb,  g_wpb);

    // 0) Weights -> bf16
    wconv<<<(3 * NC * NC / 4 + 255) / 256, 256>>>(qkv_w, wqb, 3 * NC * NC);
    wconv<<<(NC * NC / 4 + 255) / 256, 256>>>(proj_w, wpb, NC * NC);

    // 1) GroupNorm -> bf16
    gn_kernel<<<NB * NG, 512>>>(x, gn_scale, gn_bias, xnb);

    // 2) QKV GEMM (bf16, q pre-scaled by 0.125)
    cudaFuncSetAttribute(gemm_mma<0>,
                         cudaFuncAttributeMaxDynamicSharedMemorySize, GEMM_SMEM);
    cudaFuncSetAttribute(gemm_mma<1>,
                         cudaFuncAttributeMaxDynamicSharedMemorySize, GEMM_SMEM);
    dim3 gq(NT / 128, 3 * NC / 128, NB);
    gemm_mma<0><<<gq, 256, GEMM_SMEM>>>(wqb, xnb, qkv_b, nullptr, qkvb, nullptr,
                                        NC, (long)NC * NT, (long)3 * NC * NT, 0L);

    // 3) Flash attention
    cudaFuncSetAttribute(attn_mma,
                         cudaFuncAttributeMaxDynamicSharedMemorySize, ATT_SMEM);
    attn_mma<<<dim3(NT / 64, NB * NH), 256, ATT_SMEM>>>(qkvb, attnb);

    // 4) Proj GEMM (bf16 in, fp32 out + bias + residual)
    dim3 gp(NT / 128, NC / 128, NB);
    gemm_mma<1><<<gp, 256, GEMM_SMEM>>>(wpb, attnb, proj_b, x, nullptr, out,
                                        NC, (long)NC * NT, (long)NC * NT,
                                        (long)NC * NT);
}

// round 8
// speedup vs baseline: 5.2154x; 1.0309x over previous
#include <cuda_runtime.h>
#include <cstdint>

constexpr int NB = 4;      // batch
constexpr int NC = 1024;   // channels
constexpr int NT = 2048;   // time
constexpr int NH = 16;     // heads
constexpr int NG = 32;     // groups
constexpr int CPG = NC / NG;
constexpr int CH  = NC / NH;
constexpr float EPS = 1e-5f;

// Scratch (device globals) — bf16 stored as uint16_t
__device__ uint16_t g_xnb [NB * NC * NT];
__device__ uint16_t g_qkvb[NB * 3 * NC * NT];
__device__ uint16_t g_attnb[NB * NC * NT];
__device__ uint16_t g_wqb [3 * NC * NC];
__device__ uint16_t g_wpb [NC * NC];
constexpr int GNS = 8;                       // GN reduce slices per group
__device__ float g_part[NB * NG * GNS * 2];  // partial sums
__device__ float g_ms[NB * NG * 2];          // mean, rstd

__device__ __forceinline__ uint32_t packbf(float lo, float hi) {
    uint32_t r;
    asm("cvt.rn.bf16x2.f32 %0, %1, %2;" : "=r"(r) : "f"(hi), "f"(lo));
    return r;
}

__device__ __forceinline__ void mma_bf16(float* c, const uint32_t* a,
                                         const uint32_t* b) {
    asm volatile(
        "mma.sync.aligned.m16n8k16.row.col.f32.bf16.bf16.f32 "
        "{%0,%1,%2,%3}, {%4,%5,%6,%7}, {%8,%9}, {%0,%1,%2,%3};"
        : "+f"(c[0]), "+f"(c[1]), "+f"(c[2]), "+f"(c[3])
        : "r"(a[0]), "r"(a[1]), "r"(a[2]), "r"(a[3]), "r"(b[0]), "r"(b[1]));
}

__device__ __forceinline__ uint32_t smem_u32(const void* p) {
    uint32_t a;
    asm("{ .reg .u64 t; cvta.to.shared.u64 t, %1; cvt.u32.u64 %0, t; }"
        : "=r"(a) : "l"(p));
    return a;
}

__device__ __forceinline__ void ldsm4(uint32_t* r, uint32_t addr) {
    asm volatile(
        "ldmatrix.sync.aligned.m8n8.x4.shared.b16 {%0,%1,%2,%3}, [%4];"
        : "=r"(r[0]), "=r"(r[1]), "=r"(r[2]), "=r"(r[3]) : "r"(addr));
}
__device__ __forceinline__ void ldsm4t(uint32_t* r, uint32_t addr) {
    asm volatile(
        "ldmatrix.sync.aligned.m8n8.x4.trans.shared.b16 {%0,%1,%2,%3}, [%4];"
        : "=r"(r[0]), "=r"(r[1]), "=r"(r[2]), "=r"(r[3]) : "r"(addr));
}

// ============================================================================
// Weight conversion fp32 -> bf16
// ============================================================================
__global__ void wconv(const float* __restrict__ W, uint16_t* __restrict__ Wb,
                      int n) {
    int i = (blockIdx.x * blockDim.x + threadIdx.x) * 4;
    if (i < n) {
        float4 v = *reinterpret_cast<const float4*>(W + i);
        uint2 u = make_uint2(packbf(v.x, v.y), packbf(v.z, v.w));
        *reinterpret_cast<uint2*>(Wb + i) = u;
    }
}

// ============================================================================
// GroupNorm split: reduce (partials) -> stats -> apply
// ============================================================================
__global__ void gn_reduce(const float* __restrict__ x) {
    const int blk = blockIdx.x;              // NB*NG*GNS
    const int grp = blk / GNS, sl = blk % GNS;
    const size_t base = (size_t)grp * (CPG * NT) + (size_t)sl * (CPG * NT / GNS);
    const float4* xv = reinterpret_cast<const float4*>(x + base);
    const int nv = CPG * NT / GNS / 4;       // 2048 float4
    float s = 0.f, sq = 0.f;
    for (int i = threadIdx.x; i < nv; i += 256) {
        float4 v = xv[i];
        s  += v.x + v.y + v.z + v.w;
        sq += v.x * v.x + v.y * v.y + v.z * v.z + v.w * v.w;
    }
    __shared__ float ss[256], sq2[256];
    ss[threadIdx.x] = s; sq2[threadIdx.x] = sq;
    __syncthreads();
    for (int o = 128; o > 0; o >>= 1) {
        if (threadIdx.x < (unsigned)o) {
            ss[threadIdx.x]  += ss[threadIdx.x + o];
            sq2[threadIdx.x] += sq2[threadIdx.x + o];
        }
        __syncthreads();
    }
    if (threadIdx.x == 0) {
        g_part[blk * 2]     = ss[0];
        g_part[blk * 2 + 1] = sq2[0];
    }
}

__global__ void gn_stats() {
    const int g = threadIdx.x;               // 128 groups
    float s = 0.f, sq = 0.f;
#pragma unroll
    for (int i = 0; i < GNS; i++) {
        s  += g_part[(g * GNS + i) * 2];
        sq += g_part[(g * GNS + i) * 2 + 1];
    }
    const float n = (float)(CPG * NT);
    float m = s / n;
    g_ms[g * 2]     = m;
    g_ms[g * 2 + 1] = rsqrtf(sq / n - m * m + EPS);
}

__global__ void gn_apply(const float* __restrict__ x,
                         const float* __restrict__ gamma,
                         const float* __restrict__ beta,
                         uint16_t* __restrict__ xnb) {
    const int total4 = NB * NC * NT / 4;
    for (int i = blockIdx.x * blockDim.x + threadIdx.x; i < total4;
         i += gridDim.x * blockDim.x) {
        const int c = (i >> 9) & (NC - 1);
        const int grp = (i >> 19) * NG + (c >> 5);
        const float m = g_ms[grp * 2], r = g_ms[grp * 2 + 1];
        const float sc = gamma[c] * r;
        const float bi = beta[c] - m * sc;
        float4 v = reinterpret_cast<const float4*>(x)[i];
        uint2 u = make_uint2(packbf(v.x * sc + bi, v.y * sc + bi),
                             packbf(v.z * sc + bi, v.w * sc + bi));
        reinterpret_cast<uint2*>(xnb)[i] = u;
    }
}

// ============================================================================
// BF16 mma.sync GEMM, ldmatrix(+trans) fragments, coalesced B loads.
// A tile: As[m][k-pairs] pitch 20 uints (non-trans ldmatrix).
// B tile: Bs[k][n] halfs, pitch 68 uints (gmem layout; trans ldmatrix).
// MODE 0: out bf16 (QKV, q rows scaled 0.125). MODE 1: fp32 + bias + resid.
// CTA 128x128, BK=32, 256 threads / 8 warps (warp tile 32x64), dbl-buffered.
// ============================================================================
constexpr int GPA = 20;                 // A uint pitch
constexpr int GPB = 68;                 // B uint pitch ([k][n] rows of 128 n)
constexpr int AST = 128 * GPA;          // 2560
constexpr int BST = 32 * GPB;           // 2176
constexpr int STG = AST + BST;          // 4736 uints per stage
constexpr int GEMM_SMEM = 2 * STG * 4;  // 37888 B

template <int MODE>
__global__ void __launch_bounds__(256) gemm_mma(
    const uint16_t* __restrict__ W, const uint16_t* __restrict__ X,
    const float* __restrict__ bias, const float* __restrict__ resid,
    uint16_t* __restrict__ Cb, float* __restrict__ Cf, int K,
    long strideB, long strideC, long strideR) {
    extern __shared__ uint32_t smu[];

    const int t = threadIdx.x;
    const int wid = t >> 5, lane = t & 31;
    const int gi = lane >> 2, li = lane & 3;
    const int wm0 = (wid & 3) * 32;
    const int wn0 = (wid >> 2) * 64;
    const int m0 = blockIdx.y * 128;
    const int n0 = blockIdx.x * 128;
    const int z  = blockIdx.z;

    // A fragment (non-trans) lane pattern
    const int aIdx = (wm0 + (lane & 15)) * GPA + ((lane >> 4) << 2);
    // B fragment (trans) lane pattern: row k, col n
    const int bRow = lane & 7;
    const int bK8  = ((lane >> 3) & 1) << 3;
    const int bN4  = ((lane >> 4) & 1) << 2;
    const int bBase = (bK8 + bRow) * GPB + (wn0 >> 1) + bN4;
    const uint32_t smb = smem_u32(smu);

    // gmem assignments
    const int arow = t >> 1;
    const int acu  = (t & 1) * 8;
    const uint16_t* Wp = W + (size_t)(m0 + arow) * K + (t & 1) * 16;
    const int bk = t >> 3;                   // k row 0..31
    const int bn = (t & 7) * 16;             // n offset (halfs)
    const uint16_t* Xp = X + (size_t)z * strideB + (size_t)bk * NT + n0 + bn;

    float c[2][8][4];
#pragma unroll
    for (int mt = 0; mt < 2; mt++)
#pragma unroll
        for (int nt = 0; nt < 8; nt++)
#pragma unroll
            for (int i = 0; i < 4; i++) c[mt][nt][i] = 0.f;

    uint4 apre[2], bpre[2];
    const int NIT = K / 32;

    apre[0] = *reinterpret_cast<const uint4*>(Wp);
    apre[1] = *reinterpret_cast<const uint4*>(Wp + 8);
    bpre[0] = *reinterpret_cast<const uint4*>(Xp);
    bpre[1] = *reinterpret_cast<const uint4*>(Xp + 8);
    {
        uint32_t* As = smu;
        uint32_t* Bs = smu + AST;
        *reinterpret_cast<uint4*>(&As[arow * GPA + acu])     = apre[0];
        *reinterpret_cast<uint4*>(&As[arow * GPA + acu + 4]) = apre[1];
        *reinterpret_cast<uint4*>(&Bs[bk * GPB + (bn >> 1)])     = bpre[0];
        *reinterpret_cast<uint4*>(&Bs[bk * GPB + (bn >> 1) + 4]) = bpre[1];
    }
    __syncthreads();

    for (int it = 0; it < NIT; it++) {
        if (it + 1 < NIT) {
            const int k0 = (it + 1) * 32;
            apre[0] = *reinterpret_cast<const uint4*>(Wp + k0);
            apre[1] = *reinterpret_cast<const uint4*>(Wp + k0 + 8);
            bpre[0] = *reinterpret_cast<const uint4*>(Xp + (size_t)k0 * NT);
            bpre[1] = *reinterpret_cast<const uint4*>(Xp + (size_t)k0 * NT + 8);
        }

        const uint32_t asb = smb + ((it & 1) * STG) * 4;
        const uint32_t bsb = asb + AST * 4;
#pragma unroll
        for (int ks = 0; ks < 2; ks++) {
            uint32_t a[2][4];
            ldsm4(a[0], asb + 4 * (aIdx + ks * 8));
            ldsm4(a[1], asb + 4 * (aIdx + 16 * GPA + ks * 8));
            uint32_t bb[4][4];
#pragma unroll
            for (int g = 0; g < 4; g++)
                ldsm4t(bb[g], bsb + 4 * (bBase + ks * 16 * GPB + g * 8));
#pragma unroll
            for (int mt = 0; mt < 2; mt++)
#pragma unroll
                for (int g = 0; g < 4; g++) {
                    mma_bf16(c[mt][2 * g],     a[mt], &bb[g][0]);
                    mma_bf16(c[mt][2 * g + 1], a[mt], &bb[g][2]);
                }
        }

        if (it + 1 < NIT) {
            uint32_t* Asn = smu + ((it + 1) & 1) * STG;
            uint32_t* Bsn = Asn + AST;
            *reinterpret_cast<uint4*>(&Asn[arow * GPA + acu])     = apre[0];
            *reinterpret_cast<uint4*>(&Asn[arow * GPA + acu + 4]) = apre[1];
            *reinterpret_cast<uint4*>(&Bsn[bk * GPB + (bn >> 1)])     = bpre[0];
            *reinterpret_cast<uint4*>(&Bsn[bk * GPB + (bn >> 1) + 4]) = bpre[1];
            __syncthreads();
        }
    }

#pragma unroll
    for (int mt = 0; mt < 2; mt++) {
#pragma unroll
        for (int h = 0; h < 2; h++) {
            const int m = m0 + wm0 + mt * 16 + gi + h * 8;
            const float bv = bias[m];
            if (MODE == 0) {
                const float qs = (m < NC) ? 0.125f : 1.0f;
                uint16_t* Cp = Cb + (size_t)z * strideC + (size_t)m * NT + n0 + wn0;
#pragma unroll
                for (int nt = 0; nt < 8; nt++) {
                    const int col = nt * 8 + 2 * li;
                    uint32_t p = packbf((c[mt][nt][2 * h + 0] + bv) * qs,
                                        (c[mt][nt][2 * h + 1] + bv) * qs);
                    *reinterpret_cast<uint32_t*>(Cp + col) = p;
                }
            } else {
                float* Cp = Cf + (size_t)z * strideC + (size_t)m * NT + n0 + wn0;
                const float* Rp = resid + (size_t)z * strideR + (size_t)m * NT + n0 + wn0;
#pragma unroll
                for (int nt = 0; nt < 8; nt++) {
                    const int col = nt * 8 + 2 * li;
                    float2 rv = *reinterpret_cast<const float2*>(Rp + col);
                    float2 o;
                    o.x = c[mt][nt][2 * h + 0] + bv + rv.x;
                    o.y = c[mt][nt][2 * h + 1] + bv + rv.y;
                    *reinterpret_cast<float2*>(Cp + col) = o;
                }
            }
        }
    }
}

// ============================================================================
// Flash attention, bf16, register softmax.
// Q/K stored gmem-layout [c][t] (coalesced copies), trans-ldmatrix fragments.
// V [c][j] + P [i][j] unchanged (non-trans). Register-prefetched K/V.
// ============================================================================
constexpr int APU = 36;
constexpr int ATU = 64 * APU;
constexpr int ATT_SMEM = (4 * ATU + 3 * 64 + 256) * 4;   // 38656 B

__global__ void __launch_bounds__(256) attn_mma(
    const uint16_t* __restrict__ qkv, uint16_t* __restrict__ attn_out) {
    extern __shared__ uint32_t smu[];
    uint32_t* Qu = smu;          // [c][i] halfs, pitch 36 uints
    uint32_t* Ku = Qu + ATU;     // [c][j]
    uint32_t* Vu = Ku + ATU;     // [c][j]
    uint32_t* Pu = Vu + ATU;     // [i][j-pairs]
    float* mrow = reinterpret_cast<float*>(smu + 4 * ATU);
    float* lrow = mrow + 64;
    float* arow = lrow + 64;
    float* redm = arow + 64;
    float* redl = redm + 128;

    const int tid  = threadIdx.x;
    const int wid  = tid >> 5, lane = tid & 31;
    const int gi   = lane >> 2, li = lane & 3;
    const int wm16 = (wid & 3) * 16;
    const int wn32 = (wid >> 2) * 32;
    const int half = wid >> 2;
    const int qt0  = blockIdx.x * 64;
    const int b    = blockIdx.y >> 4, h = blockIdx.y & 15;
    const size_t qbase = ((size_t)b * 3 * NC + (size_t)h * CH) * NT;
    const size_t kbase = qbase + (size_t)NC * NT;
    const size_t vbase = qbase + 2 * (size_t)NC * NT;

    // trans-ldmatrix lane patterns (S-GEMM)
    const int sRow = lane & 7;
    const int qBase = ((((lane >> 4) & 1) << 3) + sRow) * APU + (wm16 >> 1)
                      + (((lane >> 3) & 1) << 2);           // A (Q)
    const int kBase = ((((lane >> 3) & 1) << 3) + sRow) * APU + (wn32 >> 1)
                      + (((lane >> 4) & 1) << 2);           // B (K)
    // non-trans patterns (O-GEMM)
    const int aIdx = (wm16 + (lane & 15)) * APU + ((lane >> 4) << 2);   // V
    const int bIdx = (wn32 + ((lane & 7) | ((lane >> 4) << 3))) * APU
                     + (((lane >> 3) & 1) << 2);                        // P
    const uint32_t qb_ = smem_u32(Qu), kb_ = smem_u32(Ku);
    const uint32_t vb_ = smem_u32(Vu), pb_ = smem_u32(Pu);

    // copy assignments: row c = tid>>2, col offset (tid&3)*16 halfs
    const int cr = tid >> 2;
    const int co = (tid & 3) * 16;
    const int srow = cr * APU + (co >> 1);

    // Q: direct coalesced copy [c][i]
    {
        const uint16_t* qp = qkv + qbase + (size_t)cr * NT + qt0 + co;
        *reinterpret_cast<uint4*>(&Qu[srow])     = *reinterpret_cast<const uint4*>(qp);
        *reinterpret_cast<uint4*>(&Qu[srow + 4]) = *reinterpret_cast<const uint4*>(qp + 8);
    }
    if (tid < 64) { mrow[tid] = -1e30f; lrow[tid] = 0.f; }

    float oacc[4][4];
#pragma unroll
    for (int nt = 0; nt < 4; nt++)
#pragma unroll
        for (int i = 0; i < 4; i++) oacc[nt][i] = 0.f;

    const int r0 = wm16 + gi, r1 = r0 + 8;

    // prefetch kv-step 0
    uint4 kpre[2], vpre[2];
    {
        const uint16_t* kp = qkv + kbase + (size_t)cr * NT + co;
        const uint16_t* vp = qkv + vbase + (size_t)cr * NT + co;
        kpre[0] = *reinterpret_cast<const uint4*>(kp);
        kpre[1] = *reinterpret_cast<const uint4*>(kp + 8);
        vpre[0] = *reinterpret_cast<const uint4*>(vp);
        vpre[1] = *reinterpret_cast<const uint4*>(vp + 8);
    }

    for (int s0 = 0; s0 < NT; s0 += 64) {
        __syncthreads();
        *reinterpret_cast<uint4*>(&Ku[srow])     = kpre[0];
        *reinterpret_cast<uint4*>(&Ku[srow + 4]) = kpre[1];
        *reinterpret_cast<uint4*>(&Vu[srow])     = vpre[0];
        *reinterpret_cast<uint4*>(&Vu[srow + 4]) = vpre[1];
        __syncthreads();

        // ---- S = Q^T K (trans fragments) ----
        float sacc[4][4];
#pragma unroll
        for (int nt = 0; nt < 4; nt++)
#pragma unroll
            for (int i = 0; i < 4; i++) sacc[nt][i] = 0.f;
#pragma unroll
        for (int ks = 0; ks < 4; ks++) {
            uint32_t a[4];
            ldsm4t(a, qb_ + 4 * (qBase + ks * 16 * APU));
            uint32_t bb[2][4];
            ldsm4t(bb[0], kb_ + 4 * (kBase + ks * 16 * APU));
            ldsm4t(bb[1], kb_ + 4 * (kBase + ks * 16 * APU + 8));
            mma_bf16(sacc[0], a, &bb[0][0]);
            mma_bf16(sacc[1], a, &bb[0][2]);
            mma_bf16(sacc[2], a, &bb[1][0]);
            mma_bf16(sacc[3], a, &bb[1][2]);
        }

        // prefetch next kv-step
        if (s0 + 64 < NT) {
            const uint16_t* kp = qkv + kbase + (size_t)cr * NT + s0 + 64 + co;
            const uint16_t* vp = qkv + vbase + (size_t)cr * NT + s0 + 64 + co;
            kpre[0] = *reinterpret_cast<const uint4*>(kp);
            kpre[1] = *reinterpret_cast<const uint4*>(kp + 8);
            vpre[0] = *reinterpret_cast<const uint4*>(vp);
            vpre[1] = *reinterpret_cast<const uint4*>(vp + 8);
        }

        // ---- phase A: row maxima ----
        float mx0 = -1e30f, mx1 = -1e30f;
#pragma unroll
        for (int nt = 0; nt < 4; nt++) {
            mx0 = fmaxf(mx0, fmaxf(sacc[nt][0], sacc[nt][1]));
            mx1 = fmaxf(mx1, fmaxf(sacc[nt][2], sacc[nt][3]));
        }
        mx0 = fmaxf(mx0, __shfl_xor_sync(0xffffffffu, mx0, 1));
        mx0 = fmaxf(mx0, __shfl_xor_sync(0xffffffffu, mx0, 2));
        mx1 = fmaxf(mx1, __shfl_xor_sync(0xffffffffu, mx1, 1));
        mx1 = fmaxf(mx1, __shfl_xor_sync(0xffffffffu, mx1, 2));
        const float mold0 = mrow[r0], mold1 = mrow[r1];
        if (li == 0) {
            redm[half * 64 + r0] = mx0;
            redm[half * 64 + r1] = mx1;
        }
        __syncthreads();

        // ---- phase B: exp, bf16 probs, partial sums ----
        const float m0 = fmaxf(mold0, fmaxf(redm[r0], redm[64 + r0]));
        const float m1 = fmaxf(mold1, fmaxf(redm[r1], redm[64 + r1]));
        float s0s = 0.f, s1s = 0.f;
#pragma unroll
        for (int nt = 0; nt < 4; nt++) {
            uint32_t p01 = packbf(__expf(sacc[nt][0] - m0),
                                  __expf(sacc[nt][1] - m0));
            s0s += __uint_as_float(p01 << 16) +
                   __uint_as_float(p01 & 0xFFFF0000u);
            Pu[r0 * APU + (wn32 >> 1) + 4 * nt + li] = p01;
            uint32_t p23 = packbf(__expf(sacc[nt][2] - m1),
                                  __expf(sacc[nt][3] - m1));
            s1s += __uint_as_float(p23 << 16) +
                   __uint_as_float(p23 & 0xFFFF0000u);
            Pu[r1 * APU + (wn32 >> 1) + 4 * nt + li] = p23;
        }
        s0s += __shfl_xor_sync(0xffffffffu, s0s, 1);
        s0s += __shfl_xor_sync(0xffffffffu, s0s, 2);
        s1s += __shfl_xor_sync(0xffffffffu, s1s, 1);
        s1s += __shfl_xor_sync(0xffffffffu, s1s, 2);
        if (li == 0) {
            redl[half * 64 + r0] = s0s;
            redl[half * 64 + r1] = s1s;
            if (half == 0) {
                arow[r0] = __expf(mold0 - m0); mrow[r0] = m0;
                arow[r1] = __expf(mold1 - m1); mrow[r1] = m1;
            }
        }
        __syncthreads();

        // ---- phase C: l update, rescale O, O = V P^T ----
        if (li == 0 && half == 0) {
            lrow[r0] = lrow[r0] * arow[r0] + redl[r0] + redl[64 + r0];
            lrow[r1] = lrow[r1] * arow[r1] + redl[r1] + redl[64 + r1];
        }
#pragma unroll
        for (int nt = 0; nt < 4; nt++) {
            const float a0 = arow[wn32 + nt * 8 + 2 * li];
            const float a1 = arow[wn32 + nt * 8 + 2 * li + 1];
            oacc[nt][0] *= a0; oacc[nt][1] *= a1;
            oacc[nt][2] *= a0; oacc[nt][3] *= a1;
        }
#pragma unroll
        for (int ks = 0; ks < 4; ks++) {
            const int ku = ks * 8;
            uint32_t a[4];
            ldsm4(a, vb_ + 4 * (aIdx + ku));
            uint32_t bb[2][4];
            ldsm4(bb[0], pb_ + 4 * (bIdx + ku));
            ldsm4(bb[1], pb_ + 4 * (bIdx + 16 * APU + ku));
            mma_bf16(oacc[0], a, &bb[0][0]);
            mma_bf16(oacc[1], a, &bb[0][2]);
            mma_bf16(oacc[2], a, &bb[1][0]);
            mma_bf16(oacc[3], a, &bb[1][2]);
        }
    }
    __syncthreads();

    // Epilogue: O[c][i] /= l[i], bf16 out
    const size_t abase = ((size_t)b * NC + (size_t)h * CH) * NT;
#pragma unroll
    for (int nt = 0; nt < 4; nt++) {
        const int i = wn32 + nt * 8 + 2 * li;
        const float l0 = 1.f / lrow[i];
        const float l1 = 1.f / lrow[i + 1];
        *reinterpret_cast<uint32_t*>(
            &attn_out[abase + (size_t)r0 * NT + qt0 + i]) =
            packbf(oacc[nt][0] * l0, oacc[nt][1] * l1);
        *reinterpret_cast<uint32_t*>(
            &attn_out[abase + (size_t)r1 * NT + qt0 + i]) =
            packbf(oacc[nt][2] * l0, oacc[nt][3] * l1);
    }
}

// ---------------------------------------------------------------------------
extern "C" void kernel_launch(void* const* d_in, const int* in_sizes, int n_in,
                              void* d_out, int out_size) {
    const float* x        = (const float*)d_in[0];
    const float* gn_scale = (const float*)d_in[1];
    const float* gn_bias  = (const float*)d_in[2];
    const float* qkv_w    = (const float*)d_in[3];
    const float* qkv_b    = (const float*)d_in[4];
    const float* proj_w   = (const float*)d_in[5];
    const float* proj_b   = (const float*)d_in[6];
    float* out = (float*)d_out;

    uint16_t *xnb, *qkvb, *attnb, *wqb, *wpb;
    cudaGetSymbolAddress((void**)&xnb,  g_xnb);
    cudaGetSymbolAddress((void**)&qkvb, g_qkvb);
    cudaGetSymbolAddress((void**)&attnb, g_attnb);
    cudaGetSymbolAddress((void**)&wqb,  g_wqb);
    cudaGetSymbolAddress((void**)&wpb,  g_wpb);

    // 0) Weights -> bf16
    wconv<<<(3 * NC * NC / 4 + 255) / 256, 256>>>(qkv_w, wqb, 3 * NC * NC);
    wconv<<<(NC * NC / 4 + 255) / 256, 256>>>(proj_w, wpb, NC * NC);

    // 1) GroupNorm (reduce -> stats -> apply)
    gn_reduce<<<NB * NG * GNS, 256>>>(x);
    gn_stats<<<1, 128>>>();
    gn_apply<<<2048, 256>>>(x, gn_scale, gn_bias, xnb);

    // 2) QKV GEMM
    cudaFuncSetAttribute(gemm_mma<0>,
                         cudaFuncAttributeMaxDynamicSharedMemorySize, GEMM_SMEM);
    cudaFuncSetAttribute(gemm_mma<1>,
                         cudaFuncAttributeMaxDynamicSharedMemorySize, GEMM_SMEM);
    dim3 gq(NT / 128, 3 * NC / 128, NB);
    gemm_mma<0><<<gq, 256, GEMM_SMEM>>>(wqb, xnb, qkv_b, nullptr, qkvb, nullptr,
                                        NC, (long)NC * NT, (long)3 * NC * NT, 0L);

    // 3) Flash attention
    cudaFuncSetAttribute(attn_mma,
                         cudaFuncAttributeMaxDynamicSharedMemorySize, ATT_SMEM);
    attn_mma<<<dim3(NT / 64, NB * NH), 256, ATT_SMEM>>>(qkvb, attnb);

    // 4) Proj GEMM
    dim3 gp(NT / 128, NC / 128, NB);
    gemm_mma<1><<<gp, 256, GEMM_SMEM>>>(wpb, attnb, proj_b, x, nullptr, out,
                                        NC, (long)NC * NT, (long)NC * NT,
                                        (long)NC * NT);
}